// round 14
// baseline (speedup 1.0000x reference)
#include <cuda_runtime.h>
#include <math.h>

#define Bz 8
#define Ln 64
#define WL 32
#define EMBD 256
#define H2 256
#define HIDD 512
#define RECD 128
#define NEGV -1000000000.0f

__device__ float g_embeds[Bz*Ln*EMBD];
__device__ float g_xw[2*Bz*Ln*1024];
__device__ float g_hT[4*H2*Ln];          // [buf(2)][dir(2)][unit 256][n 64]
__device__ unsigned g_barr[16];          // lstm [dir][step]
__device__ unsigned g_barr2;             // embed->xw grid barrier
__device__ unsigned g_barr3;             // eis/scores->final arrivals
__device__ unsigned g_barrUb[8];         // uv done per batch (8 blocks each)
__device__ unsigned g_barrPb[8];         // p12 done per batch (2 blocks each)
__device__ float g_hs[Bz*Ln*HIDD];
__device__ float g_u[Bz*Ln];
__device__ float g_v[Bz*Ln];
__device__ float g_p1[Bz*Ln*RECD];
__device__ float g_p2[Bz*Ln*RECD];
__device__ float g_s[Bz*Ln*Ln];
__device__ float g_rowlse[Bz*Ln];
__device__ float g_logZ[Bz];

__device__ __forceinline__ float fsig(float x) {
    return __fdividef(1.0f, 1.0f + __expf(-x));
}

// K1 (fused): embed (4 rows/block) -> grid barrier (128) -> xW GEMM 64x128 tile.
// grid (8,8,2) x 256 threads; dyn smem 51.2KB (Ash 64x68 + Wsh 64x132).
__global__ void k_emb_xw(const int* __restrict__ sents, const float* __restrict__ mask,
                         const float* __restrict__ emb,
                         const float* __restrict__ Wf, const float* __restrict__ bif,
                         const float* __restrict__ bhf,
                         const float* __restrict__ Wb, const float* __restrict__ bib,
                         const float* __restrict__ bhb) {
    extern __shared__ float dsm[];
    float* Ash = dsm;            // [e 64][row 64] pitch 68
    float* Wsh = dsm + 64*68;    // [e 64][gate 128] pitch 132
    int lin = blockIdx.x + blockIdx.y*8 + blockIdx.z*64;   // 0..127
    int tid = threadIdx.x;
    __shared__ int sw[WL]; __shared__ float sm[WL]; __shared__ float sden;
    // ---- embed phase: rows 4*lin .. 4*lin+3 ----
    #pragma unroll
    for (int r = 0; r < 4; r++) {
        int row = lin*4 + r;
        if (tid < WL) { sw[tid] = sents[row*WL + tid]; sm[tid] = mask[row*WL + tid]; }
        __syncthreads();
        if (tid == 0) {
            float e = 0.f;
            for (int w = 0; w < WL; w++) e += sm[w];
            sden = e + (e == 0.0f ? 1.0f : 0.0f);
        }
        __syncthreads();
        float acc = 0.f;
        #pragma unroll 8
        for (int w = 0; w < WL; w++) acc += emb[(size_t)sw[w]*EMBD + tid] * sm[w];
        g_embeds[row*EMBD + tid] = acc / sden;
        __syncthreads();
    }
    // ---- grid barrier (128 blocks) ----
    __threadfence();
    if (tid == 0) {
        unsigned c = atomicAdd(&g_barr2, 1u) + 1u;
        if (c < 128u) {
            volatile unsigned* p = &g_barr2;
            while (*p < 128u) { }
        }
    }
    __syncthreads();
    // ---- xw phase: 64 rows x 128 gates, 4x8 register tile ----
    int dir = blockIdx.z;
    const float* W  = dir ? Wb  : Wf;
    const float* bi = dir ? bib : bif;
    const float* bh = dir ? bhb : bhf;
    int r0 = blockIdx.x * 64, g0 = blockIdx.y * 128;
    int ri = tid & 15, gi = tid >> 4;
    float acc[4][8] = {};
    for (int e0 = 0; e0 < EMBD; e0 += 64) {
        #pragma unroll
        for (int q = 0; q < 4; q++) {           // A: 64x64 via float4
            int li = tid + q*256;
            int row = li >> 4, e4 = (li & 15)*4;
            float4 v = __ldcg((const float4*)&g_embeds[(r0+row)*EMBD + e0 + e4]);
            Ash[(e4+0)*68+row]=v.x; Ash[(e4+1)*68+row]=v.y;
            Ash[(e4+2)*68+row]=v.z; Ash[(e4+3)*68+row]=v.w;
        }
        #pragma unroll
        for (int q = 0; q < 8; q++) {           // W: 128x64 via float4
            int li = tid + q*256;
            int gg2 = li >> 4, e4 = (li & 15)*4;
            float4 v = *(const float4*)&W[(size_t)(g0+gg2)*EMBD + e0 + e4];
            Wsh[(e4+0)*132+gg2]=v.x; Wsh[(e4+1)*132+gg2]=v.y;
            Wsh[(e4+2)*132+gg2]=v.z; Wsh[(e4+3)*132+gg2]=v.w;
        }
        __syncthreads();
        #pragma unroll 4
        for (int e = 0; e < 64; e++) {
            float4 av = *(const float4*)&Ash[e*68 + ri*4];
            float4 w0 = *(const float4*)&Wsh[e*132 + gi*8];
            float4 w1 = *(const float4*)&Wsh[e*132 + gi*8 + 4];
            float aa[4] = {av.x, av.y, av.z, av.w};
            float ww[8] = {w0.x, w0.y, w0.z, w0.w, w1.x, w1.y, w1.z, w1.w};
            #pragma unroll
            for (int a = 0; a < 4; a++)
                #pragma unroll
                for (int g = 0; g < 8; g++) acc[a][g] += aa[a]*ww[g];
        }
        __syncthreads();
    }
    #pragma unroll
    for (int a = 0; a < 4; a++)
        #pragma unroll
        for (int g = 0; g < 8; g++) {
            int row = r0 + ri*4 + a, gg = g0 + gi*8 + g;
            g_xw[((size_t)dir*Bz*Ln + row)*1024 + gg] = acc[a][g] + bi[gg] + bh[gg];
        }
}

// K2: persistent LSTM — all 8 steps in one kernel.
__global__ void k_lstm_all(const float* __restrict__ Whh_f, const float* __restrict__ Whh_b) {
    extern __shared__ float smem[];
    float* wsh = smem;                  // [gc 16][e 256] pitch 260
    float* hsh = smem + 4160;           // [e 256][n 64] pitch 68
    float* gsh = smem + 4160 + 17408;   // [gc 16][n 64] pitch 68
    int bx = blockIdx.x;
    int dir = bx >> 6, ub = bx & 63, u0 = ub*4;
    const float* Whh = dir ? Whh_b : Whh_f;
    int tid = threadIdx.x;

    #pragma unroll 8
    for (int q = 0; q < 32; q++) {
        int li = tid + q*128;
        int gc = li >> 8, e = li & 255;
        int ul = gc >> 2, gate = gc & 3;
        wsh[gc*260 + e] = Whh[(gate*H2 + u0 + ul)*H2 + e];
    }
    int ng = tid >> 3, gg = tid & 7;
    int n_c = tid & 63, ul_c = tid >> 6;
    float c0 = 0.f, c1 = 0.f;
    __syncthreads();

    for (int s = 0; s < Bz; s++) {
        int t = dir ? (Bz-1-s) : s;
        const float* xb = &g_xw[((size_t)(dir*Bz*Ln + t*Ln + n_c))*1024 + u0 + ul_c];
        float xw0[4], xw1[4];
        #pragma unroll
        for (int g = 0; g < 4; g++) { xw0[g] = xb[g*256]; xw1[g] = xb[g*256 + 2]; }

        float a00=0.f,a01=0.f,a10=0.f,a11=0.f,a20=0.f,a21=0.f,a30=0.f,a31=0.f;
        if (s > 0) {
            const float* hp = &g_hT[((s&1)*2 + dir)*H2*Ln];
            #pragma unroll 8
            for (int q = 0; q < 32; q++) {
                int idx = (tid + q*128)*4;
                int e = idx >> 6, n = idx & 63;
                float4 hv = __ldcg((const float4*)(hp + idx));
                *(float4*)&hsh[e*68 + n] = hv;
            }
            __syncthreads();
            #pragma unroll 4
            for (int e4 = 0; e4 < H2; e4 += 4) {
                float4 w0 = *(const float4*)&wsh[(gg*2  )*260 + e4];
                float4 w1 = *(const float4*)&wsh[(gg*2+1)*260 + e4];
                float wa[4] = {w0.x, w0.y, w0.z, w0.w};
                float wb[4] = {w1.x, w1.y, w1.z, w1.w};
                #pragma unroll
                for (int k = 0; k < 4; k++) {
                    float4 hv = *(const float4*)&hsh[(e4+k)*68 + ng*4];
                    a00 += hv.x*wa[k]; a01 += hv.x*wb[k];
                    a10 += hv.y*wa[k]; a11 += hv.y*wb[k];
                    a20 += hv.z*wa[k]; a21 += hv.z*wb[k];
                    a30 += hv.w*wa[k]; a31 += hv.w*wb[k];
                }
            }
        } else {
            __syncthreads();
        }
        gsh[(gg*2  )*68 + ng*4 + 0] = a00; gsh[(gg*2+1)*68 + ng*4 + 0] = a01;
        gsh[(gg*2  )*68 + ng*4 + 1] = a10; gsh[(gg*2+1)*68 + ng*4 + 1] = a11;
        gsh[(gg*2  )*68 + ng*4 + 2] = a20; gsh[(gg*2+1)*68 + ng*4 + 2] = a21;
        gsh[(gg*2  )*68 + ng*4 + 3] = a30; gsh[(gg*2+1)*68 + ng*4 + 3] = a31;
        __syncthreads();
        {
            float iv = gsh[(ul_c*4+0)*68 + n_c] + xw0[0];
            float fv = gsh[(ul_c*4+1)*68 + n_c] + xw0[1];
            float gv = gsh[(ul_c*4+2)*68 + n_c] + xw0[2];
            float ov = gsh[(ul_c*4+3)*68 + n_c] + xw0[3];
            c0 = fsig(fv)*c0 + fsig(iv)*__tanhf(gv);
            float h0 = fsig(ov)*__tanhf(c0);
            int ul2 = ul_c + 2;
            float iv1 = gsh[(ul2*4+0)*68 + n_c] + xw1[0];
            float fv1 = gsh[(ul2*4+1)*68 + n_c] + xw1[1];
            float gv1 = gsh[(ul2*4+2)*68 + n_c] + xw1[2];
            float ov1 = gsh[(ul2*4+3)*68 + n_c] + xw1[3];
            c1 = fsig(fv1)*c1 + fsig(iv1)*__tanhf(gv1);
            float h1 = fsig(ov1)*__tanhf(c1);
            int wbuf = (((s+1)&1)*2 + dir)*H2*Ln;
            __stcg(&g_hT[wbuf + (u0+ul_c )*Ln + n_c], h0);
            __stcg(&g_hT[wbuf + (u0+ul2  )*Ln + n_c], h1);
            g_hs[((size_t)t*Ln + n_c)*HIDD + dir*H2 + u0 + ul_c] = h0;
            g_hs[((size_t)t*Ln + n_c)*HIDD + dir*H2 + u0 + ul2 ] = h1;
        }
        if (s < Bz-1) {
            __threadfence();
            __syncthreads();
            if (tid == 0) {
                unsigned c = atomicAdd(&g_barr[dir*8 + s], 1u) + 1u;
                if (c < 64u) {
                    volatile unsigned* p = &g_barr[dir*8 + s];
                    while (*p < 64u) { }
                }
            }
            __syncthreads();
        }
    }
}

// Eisner width-step: NQ = ceil(w/16) known at compile time.
template<int NQ>
__device__ __forceinline__ void eis_step(
    float* __restrict__ Cr, float* __restrict__ Cl,
    float* __restrict__ Ir, float* __restrict__ Il,
    const float* __restrict__ ush, const float* __restrict__ vsh,
    int w, int spans, int grp, int l16)
{
    bool valid = grp < spans;
    int i = valid ? grp : 0, jn = i + w;
    float t_in[NQ], t_cr[NQ], t_cl[NQ];
    float m_in = -INFINITY, m_cr = -INFINITY, m_cl = -INFINITY;
    #pragma unroll
    for (int q = 0; q < NQ; q++) {
        int o = l16 + q*16;
        t_in[q] = -INFINITY; t_cr[q] = -INFINITY; t_cl[q] = -INFINITY;
        if (valid && o < w) {
            int k = i + o;
            t_in[q] = Cr[i*65 + k] + Cl[(k+1)*65 + jn];
            if (o < w - 1) {
                int k2 = k + 1;
                t_cr[q] = Ir[i*65 + k2] + Cr[k2*65 + jn];
                t_cl[q] = Cl[i*65 + k2] + Il[k2*65 + jn];
            }
        }
        m_in = fmaxf(m_in, t_in[q]);
        m_cr = fmaxf(m_cr, t_cr[q]);
        m_cl = fmaxf(m_cl, t_cl[q]);
    }
    #pragma unroll
    for (int o = 8; o; o >>= 1) {
        m_in = fmaxf(m_in, __shfl_xor_sync(0xffffffffu, m_in, o));
        m_cr = fmaxf(m_cr, __shfl_xor_sync(0xffffffffu, m_cr, o));
        m_cl = fmaxf(m_cl, __shfl_xor_sync(0xffffffffu, m_cl, o));
    }
    float ms_in = fmaxf(m_in, -1e30f);
    float ms_cr = fmaxf(m_cr, -1e30f);
    float ms_cl = fmaxf(m_cl, -1e30f);
    float s_in = 0.f, s_cr = 0.f, s_cl = 0.f;
    #pragma unroll
    for (int q = 0; q < NQ; q++) {
        s_in += __expf(t_in[q] - ms_in);
        s_cr += __expf(t_cr[q] - ms_cr);
        s_cl += __expf(t_cl[q] - ms_cl);
    }
    #pragma unroll
    for (int o = 8; o; o >>= 1) {
        s_in += __shfl_xor_sync(0xffffffffu, s_in, o);
        s_cr += __shfl_xor_sync(0xffffffffu, s_cr, o);
        s_cl += __shfl_xor_sync(0xffffffffu, s_cl, o);
    }
    if (valid && l16 == 0) {
        float inc = ms_in + __logf(s_in);
        float irv = inc + ush[i]  + vsh[jn];
        float ilv = inc + ush[jn] + vsh[i];
        Ir[i*65 + jn] = irv;
        Il[i*65 + jn] = ilv;
        float lcr = ms_cr + __logf(s_cr);
        float M = fmaxf(lcr, irv);
        Cr[i*65 + jn] = M + __logf(__expf(lcr - M) + __expf(irv - M));
        float lcl = ms_cl + __logf(s_cl);
        float Ml = fmaxf(lcl, ilv);
        Cl[i*65 + jn] = Ml + __logf(__expf(lcl - Ml) + __expf(ilv - Ml));
    }
}

#define EIS_BAND(W0, W1B, NQV)                                              \
    for (int w = (W0); w <= (W1B); w++) {                                    \
        int spans = Ln - w;                                                  \
        if (wrp*2 < spans)                                                   \
            eis_step<NQV>(Cr, Cl, Ir, Il, ush, vsh, w, spans, grp, l16);     \
        __syncthreads();                                                     \
    }

// K3 (tail): blocks 0..7 eisner(+final in blk0); 8..39 scores; 40..55 p12;
// 56..119 uv. Per-batch spin deps: uv->eisner (g_barrUb), p12->scores (g_barrPb).
__global__ void __launch_bounds__(1024, 1)
k_tail(const float* __restrict__ bs, const int* __restrict__ heads,
       const float* __restrict__ prior, const float* __restrict__ Ws,
       const float* __restrict__ W1, const float* __restrict__ b1,
       const float* __restrict__ W2, const float* __restrict__ b2,
       float* __restrict__ out) {
    extern __shared__ float smf[];
    int tid = threadIdx.x;
    int bid = blockIdx.x;
    if (bid < 8) {
        // ---- Eisner ----
        float* Cr = smf;         float* Cl = smf + 4160;
        float* Ir = smf + 8320;  float* Il = smf + 12480;
        __shared__ float ush[64], vsh[64];
        int b = bid;
        for (int idx = tid; idx < 4160; idx += 1024) {
            int i = idx / 65, jj = idx % 65;
            float dv = (jj < 64 && i == jj) ? 0.0f : NEGV;
            Cr[idx] = dv; Cl[idx] = dv; Ir[idx] = NEGV; Il[idx] = NEGV;
        }
        if (tid == 0) {
            volatile unsigned* p = &g_barrUb[b];
            while (*p < 8u) { }
        }
        __syncthreads();
        if (tid < 64) {
            ush[tid] = __ldcg(&g_u[b*Ln + tid]) + bs[0];
            vsh[tid] = __ldcg(&g_v[b*Ln + tid]);
        }
        __syncthreads();
        int grp = tid >> 4, l16 = tid & 15, wrp = tid >> 5;
        EIS_BAND(1, 16, 1)
        EIS_BAND(17, 32, 2)
        EIS_BAND(33, 48, 3)
        EIS_BAND(49, 63, 4)
        if (tid == 0) g_logZ[b] = Cr[Ln - 1];
        __threadfence();
        __syncthreads();
        if (bid == 0) {
            if (tid == 0) {
                unsigned c = atomicAdd(&g_barr3, 1u) + 1u;
                if (c < 40u) {
                    volatile unsigned* p = &g_barr3;
                    while (*p < 40u) { }
                }
            }
            __syncthreads();
            if (tid < 256) {
                int warp = tid >> 5, lane = tid & 31;
                __shared__ float sb[8];
                int b2 = warp;
                float bsv = bs[0];
                int m1 = lane + 1, m2 = lane + 33;
                float v1, v2;
                {
                    int hd = heads[b2*Ln + m1];
                    v1 = __ldcg(&g_u[b2*Ln + hd]) + __ldcg(&g_v[b2*Ln + m1]) + bsv
                       + __ldcg(&g_s[((size_t)b2*Ln + hd)*Ln + m1])
                       - __ldcg(&g_rowlse[b2*Ln + hd])
                       + prior[((size_t)b2*Ln + hd)*Ln + m1] * (1.0f/64.0f);
                }
                if (m2 < Ln) {
                    int hd = heads[b2*Ln + m2];
                    v2 = __ldcg(&g_u[b2*Ln + hd]) + __ldcg(&g_v[b2*Ln + m2]) + bsv
                       + __ldcg(&g_s[((size_t)b2*Ln + hd)*Ln + m2])
                       - __ldcg(&g_rowlse[b2*Ln + hd])
                       + prior[((size_t)b2*Ln + hd)*Ln + m2] * (1.0f/64.0f);
                } else v2 = -INFINITY;
                float mx = fmaxf(v1, v2);
                #pragma unroll
                for (int o = 16; o; o >>= 1) mx = fmaxf(mx, __shfl_xor_sync(0xffffffffu, mx, o));
                float sum = __expf(v1 - mx) + __expf(v2 - mx);
                #pragma unroll
                for (int o = 16; o; o >>= 1) sum += __shfl_xor_sync(0xffffffffu, sum, o);
                if (lane == 0) sb[b2] = (mx + __logf(sum)) - __ldcg(&g_logZ[b2]);
                __syncthreads();
                if (tid == 0) {
                    float t = 0.f;
                    for (int q = 0; q < 8; q++) t += sb[q];
                    out[0] = -t * (1.0f/8.0f);
                    for (int q = 0; q < 16; q++) g_barr[q] = 0u;
                    for (int q = 0; q < 8; q++) { g_barrUb[q] = 0u; g_barrPb[q] = 0u; }
                    g_barr2 = 0u; g_barr3 = 0u;
                }
            }
        } else {
            if (tid == 0) atomicAdd(&g_barr3, 1u);
        }
        return;
    }
    if (bid < 40) {
        // ---- scores (waits for its batch's p12) ----
        int sb2 = bid - 8;
        int b = sb2 >> 2, i0 = (sb2 & 3) * 16;
        float* p1sh = smf;              // 16 x 132
        float* p2sh = smf + 16*132;     // 64 x 132
        __shared__ float mm[32], ss[32];
        if (tid == 0) {
            volatile unsigned* p = &g_barrPb[b];
            while (*p < 2u) { }
        }
        __syncthreads();
        if (tid < 512) {
            int rr = tid >> 5, e4 = tid & 31;
            *(float4*)&p1sh[rr*132 + e4*4] =
                __ldcg((const float4*)&g_p1[(b*Ln + i0 + rr)*RECD + e4*4]);
        }
        #pragma unroll
        for (int q = 0; q < 2; q++) {
            int li = tid + q*1024;
            int rr = li >> 5, e4 = li & 31;
            *(float4*)&p2sh[rr*132 + e4*4] =
                __ldcg((const float4*)&g_p2[(b*Ln + rr)*RECD + e4*4]);
        }
        __syncthreads();
        int i_l = tid >> 6, j = tid & 63;
        float dot = 0.f;
        #pragma unroll 8
        for (int e4 = 0; e4 < 32; e4++) {
            float4 a = *(const float4*)&p1sh[i_l*132 + e4*4];
            float4 bv = *(const float4*)&p2sh[j*132 + e4*4];
            dot += a.x*bv.x + a.y*bv.y + a.z*bv.z + a.w*bv.w;
        }
        int i = i0 + i_l;
        g_s[((size_t)b*Ln + i)*Ln + j] = dot;
        float m = dot;
        #pragma unroll
        for (int o = 16; o; o >>= 1) m = fmaxf(m, __shfl_xor_sync(0xffffffffu, m, o));
        float sum = __expf(dot - m);
        #pragma unroll
        for (int o = 16; o; o >>= 1) sum += __shfl_xor_sync(0xffffffffu, sum, o);
        int warp = tid >> 5, lane = tid & 31;
        if (lane == 0) { mm[warp] = m; ss[warp] = sum; }
        __syncthreads();
        if (tid < 16) {
            float m0 = mm[tid*2], m1 = mm[tid*2+1];
            float M = fmaxf(m0, m1);
            float S = ss[tid*2]*__expf(m0 - M) + ss[tid*2+1]*__expf(m1 - M);
            g_rowlse[b*Ln + i0 + tid] = M + __logf(S);
        }
        __threadfence();
        __syncthreads();
        if (tid == 0) atomicAdd(&g_barr3, 1u);
        return;
    }
    if (bid < 56) {
        // ---- p12 GEMM: 16 blocks, 4 col-subtiles sharing one h row-tile ----
        int pbi = bid - 40;             // 0..15
        int br = pbi >> 1, cq = pbi & 1;
        int st = tid >> 8;              // subtile 0..3
        int stid = tid & 255;
        int bc = cq*4 + st;
        const float* W    = (bc < 4) ? W1 : W2;
        const float* bias = (bc < 4) ? b1 : b2;
        float* dst        = (bc < 4) ? g_p1 : g_p2;
        int c0 = (bc & 3) * 32;
        int r0 = br * 64;
        float* hsh = smf;                         // 64k x 64row pitch 68
        float* wsh = smf + 4352 + st*2176;        // 32c x 64k pitch 68
        int tr = stid >> 4, tc = stid & 15;
        float a0[2] = {}, a1[2] = {}, a2[2] = {}, a3[2] = {};
        int srow = tid & 63, skq = tid >> 6;      // 0..15
        int swc = stid >> 3, swk8 = (stid & 7) * 8;
        for (int k0 = 0; k0 < HIDD; k0 += 64) {
            float4 v = *(const float4*)&g_hs[(size_t)(r0+srow)*HIDD + k0 + skq*4];
            int kb = skq*4;
            hsh[(kb+0)*68+srow]=v.x; hsh[(kb+1)*68+srow]=v.y;
            hsh[(kb+2)*68+srow]=v.z; hsh[(kb+3)*68+srow]=v.w;
            *(float4*)&wsh[swc*68 + swk8] =
                *(const float4*)&W[(size_t)(c0 + swc)*HIDD + k0 + swk8];
            *(float4*)&wsh[swc*68 + swk8 + 4] =
                *(const float4*)&W[(size_t)(c0 + swc)*HIDD + k0 + swk8 + 4];
            __syncthreads();
            #pragma unroll 8
            for (int k = 0; k < 64; k += 4) {
                float4 w0 = *(const float4*)&wsh[(tc*2  )*68 + k];
                float4 w1 = *(const float4*)&wsh[(tc*2+1)*68 + k];
                float4 h0 = *(const float4*)&hsh[(k+0)*68 + tr*4];
                float4 h1 = *(const float4*)&hsh[(k+1)*68 + tr*4];
                float4 h2 = *(const float4*)&hsh[(k+2)*68 + tr*4];
                float4 h3 = *(const float4*)&hsh[(k+3)*68 + tr*4];
                a0[0] += h0.x*w0.x + h1.x*w0.y + h2.x*w0.z + h3.x*w0.w;
                a1[0] += h0.y*w0.x + h1.y*w0.y + h2.y*w0.z + h3.y*w0.w;
                a2[0] += h0.z*w0.x + h1.z*w0.y + h2.z*w0.z + h3.z*w0.w;
                a3[0] += h0.w*w0.x + h1.w*w0.y + h2.w*w0.z + h3.w*w0.w;
                a0[1] += h0.x*w1.x + h1.x*w1.y + h2.x*w1.z + h3.x*w1.w;
                a1[1] += h0.y*w1.x + h1.y*w1.y + h2.y*w1.z + h3.y*w1.w;
                a2[1] += h0.z*w1.x + h1.z*w1.y + h2.z*w1.z + h3.z*w1.w;
                a3[1] += h0.w*w1.x + h1.w*w1.y + h2.w*w1.z + h3.w*w1.w;
            }
            __syncthreads();
        }
        int cc = c0 + tc*2;
        float2 bv = { bias[cc], bias[cc+1] };
        *(float2*)&dst[(r0 + tr*4 + 0)*RECD + cc] = make_float2(a0[0]+bv.x, a0[1]+bv.y);
        *(float2*)&dst[(r0 + tr*4 + 1)*RECD + cc] = make_float2(a1[0]+bv.x, a1[1]+bv.y);
        *(float2*)&dst[(r0 + tr*4 + 2)*RECD + cc] = make_float2(a2[0]+bv.x, a2[1]+bv.y);
        *(float2*)&dst[(r0 + tr*4 + 3)*RECD + cc] = make_float2(a3[0]+bv.x, a3[1]+bv.y);
        __threadfence();
        __syncthreads();
        if (tid == 0) atomicAdd(&g_barrPb[br], 1u);
        return;
    }
    // ---- uv: 64 blocks x 8 rows ----
    {
        __shared__ float pu[32], pv[32];
        int ub2 = bid - 56;
        int row = ub2*8 + (tid >> 7);
        int t128 = tid & 127;
        int l = row & 63;
        const float4* hc = (const float4*)&g_hs[(size_t)row*HIDD];
        const float4* W4 = (const float4*)Ws;
        float4 h0 = hc[t128];
        float4 wu0 = W4[t128], wv0 = W4[384 + t128];
        float au = h0.x*wu0.x + h0.y*wu0.y + h0.z*wu0.z + h0.w*wu0.w;
        float av = h0.x*wv0.x + h0.y*wv0.y + h0.z*wv0.z + h0.w*wv0.w;
        if (l > 0) {
            float4 hb = hc[t128 - 128];
            float4 wu = W4[128 + t128], wv = W4[512 + t128];
            au += hb.x*wu.x + hb.y*wu.y + hb.z*wu.z + hb.w*wu.w;
            av += hb.x*wv.x + hb.y*wv.y + hb.z*wv.z + hb.w*wv.w;
        }
        if (l < 63) {
            float4 hn = hc[t128 + 128];
            float4 wu = W4[256 + t128], wv = W4[640 + t128];
            au += hn.x*wu.x + hn.y*wu.y + hn.z*wu.z + hn.w*wu.w;
            av += hn.x*wv.x + hn.y*wv.y + hn.z*wv.z + hn.w*wv.w;
        }
        #pragma unroll
        for (int o = 16; o; o >>= 1) {
            au += __shfl_xor_sync(0xffffffffu, au, o);
            av += __shfl_xor_sync(0xffffffffu, av, o);
        }
        int warp = tid >> 5, lane = tid & 31;
        if (lane == 0) { pu[warp] = au; pv[warp] = av; }
        __syncthreads();
        if (t128 == 0) {
            int wb = (tid >> 7)*4;
            g_u[row] = pu[wb]+pu[wb+1]+pu[wb+2]+pu[wb+3];
            g_v[row] = pv[wb]+pv[wb+1]+pv[wb+2]+pv[wb+3];
        }
        __threadfence();
        __syncthreads();
        if (tid == 0) atomicAdd(&g_barrUb[ub2 >> 3], 1u);
    }
}

extern "C" void kernel_launch(void* const* d_in, const int* in_sizes, int n_in,
                              void* d_out, int out_size) {
    const int*   sents = (const int*)  d_in[0];
    const float* mask  = (const float*)d_in[1];
    const float* prior = (const float*)d_in[2];
    const int*   heads = (const int*)  d_in[3];
    const float* emb   = (const float*)d_in[4];
    const float* Wih_f = (const float*)d_in[5];
    const float* Whh_f = (const float*)d_in[6];
    const float* bih_f = (const float*)d_in[7];
    const float* bhh_f = (const float*)d_in[8];
    const float* Wih_b = (const float*)d_in[9];
    const float* Whh_b = (const float*)d_in[10];
    const float* bih_b = (const float*)d_in[11];
    const float* bhh_b = (const float*)d_in[12];
    const float* W1    = (const float*)d_in[13];
    const float* b1    = (const float*)d_in[14];
    const float* W2    = (const float*)d_in[15];
    const float* b2    = (const float*)d_in[16];
    const float* Ws    = (const float*)d_in[17];
    const float* bsv   = (const float*)d_in[18];
    float* out = (float*)d_out;
    (void)in_sizes; (void)n_in; (void)out_size;

    cudaFuncSetAttribute(k_emb_xw,  cudaFuncAttributeMaxDynamicSharedMemorySize, 12800*4);
    cudaFuncSetAttribute(k_lstm_all, cudaFuncAttributeMaxDynamicSharedMemorySize, 22656*4);
    cudaFuncSetAttribute(k_tail,     cudaFuncAttributeMaxDynamicSharedMemorySize, 16640*4);

    dim3 g1(8, 8, 2);
    k_emb_xw<<<g1, 256, 12800*4>>>(sents, mask, emb, Wih_f, bih_f, bhh_f, Wih_b, bih_b, bhh_b);
    k_lstm_all<<<128, 128, 22656*4>>>(Whh_f, Whh_b);
    k_tail<<<120, 1024, 16640*4>>>(bsv, heads, prior, Ws, W1, b1, W2, b2, out);
}

// round 15
// speedup vs baseline: 1.0246x; 1.0246x over previous
#include <cuda_runtime.h>
#include <math.h>

#define Bz 8
#define Ln 64
#define WL 32
#define EMBD 256
#define H2 256
#define HIDD 512
#define RECD 128
#define NEGV -1000000000.0f

__device__ float g_embeds[Bz*Ln*EMBD];
__device__ float g_xw[2*Bz*Ln*1024];
__device__ float g_hT[4*H2*Ln];          // [buf(2)][dir(2)][unit 256][n 64]
__device__ unsigned g_barr[16];          // lstm [dir][step]
__device__ unsigned g_barr2;             // embed->xw grid barrier
__device__ unsigned g_barr3;             // eis/scores->final arrivals
__device__ unsigned g_barrUb[8];         // uv done per batch (8 blocks each)
__device__ unsigned g_barrPb[8];         // p12 done per batch (2 blocks each)
__device__ float g_hs[Bz*Ln*HIDD];
__device__ float g_u[Bz*Ln];
__device__ float g_v[Bz*Ln];
__device__ float g_p1[Bz*Ln*RECD];
__device__ float g_p2[Bz*Ln*RECD];
__device__ float g_s[Bz*Ln*Ln];
__device__ float g_rowlse[Bz*Ln];
__device__ float g_logZ[Bz];

__device__ __forceinline__ float fsig(float x) {
    return __fdividef(1.0f, 1.0f + __expf(-x));
}

// K1 (fused): embed (2 rows/block) -> grid barrier (256) -> xW GEMM 64x64 tile.
// grid (8,16,2) x 256 threads. (R13 layout — proven fastest.)
__global__ void k_emb_xw(const int* __restrict__ sents, const float* __restrict__ mask,
                         const float* __restrict__ emb,
                         const float* __restrict__ Wf, const float* __restrict__ bif,
                         const float* __restrict__ bhf,
                         const float* __restrict__ Wb, const float* __restrict__ bib,
                         const float* __restrict__ bhb) {
    int lin = blockIdx.x + blockIdx.y*8 + blockIdx.z*128;   // 0..255
    int tid = threadIdx.x;
    __shared__ __align__(16) float Ash[64*68];
    __shared__ __align__(16) float Wsh[64*68];
    __shared__ int sw[WL]; __shared__ float sm[WL]; __shared__ float sden;
    #pragma unroll
    for (int r = 0; r < 2; r++) {
        int row = lin*2 + r;
        if (tid < WL) { sw[tid] = sents[row*WL + tid]; sm[tid] = mask[row*WL + tid]; }
        __syncthreads();
        if (tid == 0) {
            float e = 0.f;
            for (int w = 0; w < WL; w++) e += sm[w];
            sden = e + (e == 0.0f ? 1.0f : 0.0f);
        }
        __syncthreads();
        float acc = 0.f;
        #pragma unroll 8
        for (int w = 0; w < WL; w++) acc += emb[(size_t)sw[w]*EMBD + tid] * sm[w];
        g_embeds[row*EMBD + tid] = acc / sden;
        __syncthreads();
    }
    __threadfence();
    if (tid == 0) {
        unsigned c = atomicAdd(&g_barr2, 1u) + 1u;
        if (c < 256u) {
            volatile unsigned* p = &g_barr2;
            while (*p < 256u) { }
        }
    }
    __syncthreads();
    int dir = blockIdx.z;
    const float* W  = dir ? Wb  : Wf;
    const float* bi = dir ? bib : bif;
    const float* bh = dir ? bhb : bhf;
    int r0 = blockIdx.x * 64, g0 = blockIdx.y * 64;
    int ri = tid & 15, gi = tid >> 4;
    float acc[4][4] = {};
    for (int e0 = 0; e0 < EMBD; e0 += 64) {
        #pragma unroll 4
        for (int q = 0; q < 16; q++) {
            int li = tid + q*256;
            int xx = li >> 6, ee = li & 63;
            Ash[ee*68 + xx] = __ldcg(&g_embeds[(r0+xx)*EMBD + e0 + ee]);
            Wsh[ee*68 + xx] = W[(g0+xx)*EMBD + e0 + ee];
        }
        __syncthreads();
        #pragma unroll 8
        for (int e = 0; e < 64; e++) {
            float4 av = *(const float4*)&Ash[e*68 + ri*4];
            float4 wv = *(const float4*)&Wsh[e*68 + gi*4];
            float aa[4] = {av.x, av.y, av.z, av.w};
            float ww[4] = {wv.x, wv.y, wv.z, wv.w};
            #pragma unroll
            for (int a = 0; a < 4; a++)
                #pragma unroll
                for (int g = 0; g < 4; g++) acc[a][g] += aa[a]*ww[g];
        }
        __syncthreads();
    }
    #pragma unroll
    for (int a = 0; a < 4; a++)
        #pragma unroll
        for (int g = 0; g < 4; g++) {
            int row = r0 + ri*4 + a, gg = g0 + gi*4 + g;
            g_xw[((size_t)dir*Bz*Ln + row)*1024 + gg] = acc[a][g] + bi[gg] + bh[gg];
        }
}

// K2: persistent LSTM — all 8 steps in one kernel.
__global__ void k_lstm_all(const float* __restrict__ Whh_f, const float* __restrict__ Whh_b) {
    extern __shared__ float smem[];
    float* wsh = smem;                  // [gc 16][e 256] pitch 260
    float* hsh = smem + 4160;           // [e 256][n 64] pitch 68
    float* gsh = smem + 4160 + 17408;   // [gc 16][n 64] pitch 68
    int bx = blockIdx.x;
    int dir = bx >> 6, ub = bx & 63, u0 = ub*4;
    const float* Whh = dir ? Whh_b : Whh_f;
    int tid = threadIdx.x;

    #pragma unroll 8
    for (int q = 0; q < 32; q++) {
        int li = tid + q*128;
        int gc = li >> 8, e = li & 255;
        int ul = gc >> 2, gate = gc & 3;
        wsh[gc*260 + e] = Whh[(gate*H2 + u0 + ul)*H2 + e];
    }
    int ng = tid >> 3, gg = tid & 7;
    int n_c = tid & 63, ul_c = tid >> 6;
    float c0 = 0.f, c1 = 0.f;
    __syncthreads();

    for (int s = 0; s < Bz; s++) {
        int t = dir ? (Bz-1-s) : s;
        const float* xb = &g_xw[((size_t)(dir*Bz*Ln + t*Ln + n_c))*1024 + u0 + ul_c];
        float xw0[4], xw1[4];
        #pragma unroll
        for (int g = 0; g < 4; g++) { xw0[g] = xb[g*256]; xw1[g] = xb[g*256 + 2]; }

        float a00=0.f,a01=0.f,a10=0.f,a11=0.f,a20=0.f,a21=0.f,a30=0.f,a31=0.f;
        if (s > 0) {
            const float* hp = &g_hT[((s&1)*2 + dir)*H2*Ln];
            #pragma unroll 8
            for (int q = 0; q < 32; q++) {
                int idx = (tid + q*128)*4;
                int e = idx >> 6, n = idx & 63;
                float4 hv = __ldcg((const float4*)(hp + idx));
                *(float4*)&hsh[e*68 + n] = hv;
            }
            __syncthreads();
            #pragma unroll 4
            for (int e4 = 0; e4 < H2; e4 += 4) {
                float4 w0 = *(const float4*)&wsh[(gg*2  )*260 + e4];
                float4 w1 = *(const float4*)&wsh[(gg*2+1)*260 + e4];
                float wa[4] = {w0.x, w0.y, w0.z, w0.w};
                float wb[4] = {w1.x, w1.y, w1.z, w1.w};
                #pragma unroll
                for (int k = 0; k < 4; k++) {
                    float4 hv = *(const float4*)&hsh[(e4+k)*68 + ng*4];
                    a00 += hv.x*wa[k]; a01 += hv.x*wb[k];
                    a10 += hv.y*wa[k]; a11 += hv.y*wb[k];
                    a20 += hv.z*wa[k]; a21 += hv.z*wb[k];
                    a30 += hv.w*wa[k]; a31 += hv.w*wb[k];
                }
            }
        } else {
            __syncthreads();
        }
        gsh[(gg*2  )*68 + ng*4 + 0] = a00; gsh[(gg*2+1)*68 + ng*4 + 0] = a01;
        gsh[(gg*2  )*68 + ng*4 + 1] = a10; gsh[(gg*2+1)*68 + ng*4 + 1] = a11;
        gsh[(gg*2  )*68 + ng*4 + 2] = a20; gsh[(gg*2+1)*68 + ng*4 + 2] = a21;
        gsh[(gg*2  )*68 + ng*4 + 3] = a30; gsh[(gg*2+1)*68 + ng*4 + 3] = a31;
        __syncthreads();
        {
            float iv = gsh[(ul_c*4+0)*68 + n_c] + xw0[0];
            float fv = gsh[(ul_c*4+1)*68 + n_c] + xw0[1];
            float gv = gsh[(ul_c*4+2)*68 + n_c] + xw0[2];
            float ov = gsh[(ul_c*4+3)*68 + n_c] + xw0[3];
            c0 = fsig(fv)*c0 + fsig(iv)*__tanhf(gv);
            float h0 = fsig(ov)*__tanhf(c0);
            int ul2 = ul_c + 2;
            float iv1 = gsh[(ul2*4+0)*68 + n_c] + xw1[0];
            float fv1 = gsh[(ul2*4+1)*68 + n_c] + xw1[1];
            float gv1 = gsh[(ul2*4+2)*68 + n_c] + xw1[2];
            float ov1 = gsh[(ul2*4+3)*68 + n_c] + xw1[3];
            c1 = fsig(fv1)*c1 + fsig(iv1)*__tanhf(gv1);
            float h1 = fsig(ov1)*__tanhf(c1);
            int wbuf = (((s+1)&1)*2 + dir)*H2*Ln;
            __stcg(&g_hT[wbuf + (u0+ul_c )*Ln + n_c], h0);
            __stcg(&g_hT[wbuf + (u0+ul2  )*Ln + n_c], h1);
            g_hs[((size_t)t*Ln + n_c)*HIDD + dir*H2 + u0 + ul_c] = h0;
            g_hs[((size_t)t*Ln + n_c)*HIDD + dir*H2 + u0 + ul2 ] = h1;
        }
        if (s < Bz-1) {
            __threadfence();
            __syncthreads();
            if (tid == 0) {
                unsigned c = atomicAdd(&g_barr[dir*8 + s], 1u) + 1u;
                if (c < 64u) {
                    volatile unsigned* p = &g_barr[dir*8 + s];
                    while (*p < 64u) { }
                }
            }
            __syncthreads();
        }
    }
}

// Eisner width-step: NQ = ceil(w/16) known at compile time.
template<int NQ>
__device__ __forceinline__ void eis_step(
    float* __restrict__ Cr, float* __restrict__ Cl,
    float* __restrict__ Ir, float* __restrict__ Il,
    const float* __restrict__ ush, const float* __restrict__ vsh,
    int w, int spans, int grp, int l16)
{
    bool valid = grp < spans;
    int i = valid ? grp : 0, jn = i + w;
    float t_in[NQ], t_cr[NQ], t_cl[NQ];
    float m_in = -INFINITY, m_cr = -INFINITY, m_cl = -INFINITY;
    #pragma unroll
    for (int q = 0; q < NQ; q++) {
        int o = l16 + q*16;
        t_in[q] = -INFINITY; t_cr[q] = -INFINITY; t_cl[q] = -INFINITY;
        if (valid && o < w) {
            int k = i + o;
            t_in[q] = Cr[i*65 + k] + Cl[(k+1)*65 + jn];
            if (o < w - 1) {
                int k2 = k + 1;
                t_cr[q] = Ir[i*65 + k2] + Cr[k2*65 + jn];
                t_cl[q] = Cl[i*65 + k2] + Il[k2*65 + jn];
            }
        }
        m_in = fmaxf(m_in, t_in[q]);
        m_cr = fmaxf(m_cr, t_cr[q]);
        m_cl = fmaxf(m_cl, t_cl[q]);
    }
    #pragma unroll
    for (int o = 8; o; o >>= 1) {
        m_in = fmaxf(m_in, __shfl_xor_sync(0xffffffffu, m_in, o));
        m_cr = fmaxf(m_cr, __shfl_xor_sync(0xffffffffu, m_cr, o));
        m_cl = fmaxf(m_cl, __shfl_xor_sync(0xffffffffu, m_cl, o));
    }
    float ms_in = fmaxf(m_in, -1e30f);
    float ms_cr = fmaxf(m_cr, -1e30f);
    float ms_cl = fmaxf(m_cl, -1e30f);
    float s_in = 0.f, s_cr = 0.f, s_cl = 0.f;
    #pragma unroll
    for (int q = 0; q < NQ; q++) {
        s_in += __expf(t_in[q] - ms_in);
        s_cr += __expf(t_cr[q] - ms_cr);
        s_cl += __expf(t_cl[q] - ms_cl);
    }
    #pragma unroll
    for (int o = 8; o; o >>= 1) {
        s_in += __shfl_xor_sync(0xffffffffu, s_in, o);
        s_cr += __shfl_xor_sync(0xffffffffu, s_cr, o);
        s_cl += __shfl_xor_sync(0xffffffffu, s_cl, o);
    }
    if (valid && l16 == 0) {
        float inc = ms_in + __logf(s_in);
        float irv = inc + ush[i]  + vsh[jn];
        float ilv = inc + ush[jn] + vsh[i];
        Ir[i*65 + jn] = irv;
        Il[i*65 + jn] = ilv;
        float lcr = ms_cr + __logf(s_cr);
        float M = fmaxf(lcr, irv);
        Cr[i*65 + jn] = M + __logf(__expf(lcr - M) + __expf(irv - M));
        float lcl = ms_cl + __logf(s_cl);
        float Ml = fmaxf(lcl, ilv);
        Cl[i*65 + jn] = Ml + __logf(__expf(lcl - Ml) + __expf(ilv - Ml));
    }
}

#define EIS_BAND(W0, W1B, NQV)                                              \
    for (int w = (W0); w <= (W1B); w++) {                                    \
        int spans = Ln - w;                                                  \
        if (wrp*2 < spans)                                                   \
            eis_step<NQV>(Cr, Cl, Ir, Il, ush, vsh, w, spans, grp, l16);     \
        __syncthreads();                                                     \
    }

// K3 (tail): blocks 0..7 eisner(+final in blk0); 8..39 scores; 40..55 p12;
// 56..119 uv. Per-batch spin deps: uv->eisner (g_barrUb), p12->scores (g_barrPb).
__global__ void __launch_bounds__(1024, 1)
k_tail(const float* __restrict__ bs, const int* __restrict__ heads,
       const float* __restrict__ prior, const float* __restrict__ Ws,
       const float* __restrict__ W1, const float* __restrict__ b1,
       const float* __restrict__ W2, const float* __restrict__ b2,
       float* __restrict__ out) {
    extern __shared__ float smf[];
    int tid = threadIdx.x;
    int bid = blockIdx.x;
    if (bid < 8) {
        // ---- Eisner ----
        float* Cr = smf;         float* Cl = smf + 4160;
        float* Ir = smf + 8320;  float* Il = smf + 12480;
        __shared__ float ush[64], vsh[64];
        int b = bid;
        for (int idx = tid; idx < 4160; idx += 1024) {
            int i = idx / 65, jj = idx % 65;
            float dv = (jj < 64 && i == jj) ? 0.0f : NEGV;
            Cr[idx] = dv; Cl[idx] = dv; Ir[idx] = NEGV; Il[idx] = NEGV;
        }
        if (tid == 0) {
            volatile unsigned* p = &g_barrUb[b];
            while (*p < 8u) { }
        }
        __syncthreads();
        if (tid < 64) {
            ush[tid] = __ldcg(&g_u[b*Ln + tid]) + bs[0];
            vsh[tid] = __ldcg(&g_v[b*Ln + tid]);
        }
        __syncthreads();
        int grp = tid >> 4, l16 = tid & 15, wrp = tid >> 5;
        EIS_BAND(1, 16, 1)
        EIS_BAND(17, 32, 2)
        EIS_BAND(33, 48, 3)
        EIS_BAND(49, 63, 4)
        if (tid == 0) g_logZ[b] = Cr[Ln - 1];
        __threadfence();
        __syncthreads();
        if (bid == 0) {
            if (tid == 0) {
                unsigned c = atomicAdd(&g_barr3, 1u) + 1u;
                if (c < 40u) {
                    volatile unsigned* p = &g_barr3;
                    while (*p < 40u) { }
                }
            }
            __syncthreads();
            if (tid < 256) {
                int warp = tid >> 5, lane = tid & 31;
                __shared__ float sb[8];
                int b2 = warp;
                float bsv = bs[0];
                int m1 = lane + 1, m2 = lane + 33;
                float v1, v2;
                {
                    int hd = heads[b2*Ln + m1];
                    v1 = __ldcg(&g_u[b2*Ln + hd]) + __ldcg(&g_v[b2*Ln + m1]) + bsv
                       + __ldcg(&g_s[((size_t)b2*Ln + hd)*Ln + m1])
                       - __ldcg(&g_rowlse[b2*Ln + hd])
                       + prior[((size_t)b2*Ln + hd)*Ln + m1] * (1.0f/64.0f);
                }
                if (m2 < Ln) {
                    int hd = heads[b2*Ln + m2];
                    v2 = __ldcg(&g_u[b2*Ln + hd]) + __ldcg(&g_v[b2*Ln + m2]) + bsv
                       + __ldcg(&g_s[((size_t)b2*Ln + hd)*Ln + m2])
                       - __ldcg(&g_rowlse[b2*Ln + hd])
                       + prior[((size_t)b2*Ln + hd)*Ln + m2] * (1.0f/64.0f);
                } else v2 = -INFINITY;
                float mx = fmaxf(v1, v2);
                #pragma unroll
                for (int o = 16; o; o >>= 1) mx = fmaxf(mx, __shfl_xor_sync(0xffffffffu, mx, o));
                float sum = __expf(v1 - mx) + __expf(v2 - mx);
                #pragma unroll
                for (int o = 16; o; o >>= 1) sum += __shfl_xor_sync(0xffffffffu, sum, o);
                if (lane == 0) sb[b2] = (mx + __logf(sum)) - __ldcg(&g_logZ[b2]);
                __syncthreads();
                if (tid == 0) {
                    float t = 0.f;
                    for (int q = 0; q < 8; q++) t += sb[q];
                    out[0] = -t * (1.0f/8.0f);
                    for (int q = 0; q < 16; q++) g_barr[q] = 0u;
                    for (int q = 0; q < 8; q++) { g_barrUb[q] = 0u; g_barrPb[q] = 0u; }
                    g_barr2 = 0u; g_barr3 = 0u;
                }
            }
        } else {
            if (tid == 0) atomicAdd(&g_barr3, 1u);
        }
        return;
    }
    if (bid < 40) {
        // ---- scores (waits for its batch's p12) ----
        int sb2 = bid - 8;
        int b = sb2 >> 2, i0 = (sb2 & 3) * 16;
        float* p1sh = smf;              // 16 x 132
        float* p2sh = smf + 16*132;     // 64 x 132
        __shared__ float mm[32], ss[32];
        if (tid == 0) {
            volatile unsigned* p = &g_barrPb[b];
            while (*p < 2u) { }
        }
        __syncthreads();
        if (tid < 512) {
            int rr = tid >> 5, e4 = tid & 31;
            *(float4*)&p1sh[rr*132 + e4*4] =
                __ldcg((const float4*)&g_p1[(b*Ln + i0 + rr)*RECD + e4*4]);
        }
        #pragma unroll
        for (int q = 0; q < 2; q++) {
            int li = tid + q*1024;
            int rr = li >> 5, e4 = li & 31;
            *(float4*)&p2sh[rr*132 + e4*4] =
                __ldcg((const float4*)&g_p2[(b*Ln + rr)*RECD + e4*4]);
        }
        __syncthreads();
        int i_l = tid >> 6, j = tid & 63;
        float dot = 0.f;
        #pragma unroll 8
        for (int e4 = 0; e4 < 32; e4++) {
            float4 a = *(const float4*)&p1sh[i_l*132 + e4*4];
            float4 bv = *(const float4*)&p2sh[j*132 + e4*4];
            dot += a.x*bv.x + a.y*bv.y + a.z*bv.z + a.w*bv.w;
        }
        int i = i0 + i_l;
        g_s[((size_t)b*Ln + i)*Ln + j] = dot;
        float m = dot;
        #pragma unroll
        for (int o = 16; o; o >>= 1) m = fmaxf(m, __shfl_xor_sync(0xffffffffu, m, o));
        float sum = __expf(dot - m);
        #pragma unroll
        for (int o = 16; o; o >>= 1) sum += __shfl_xor_sync(0xffffffffu, sum, o);
        int warp = tid >> 5, lane = tid & 31;
        if (lane == 0) { mm[warp] = m; ss[warp] = sum; }
        __syncthreads();
        if (tid < 16) {
            float m0 = mm[tid*2], m1 = mm[tid*2+1];
            float M = fmaxf(m0, m1);
            float S = ss[tid*2]*__expf(m0 - M) + ss[tid*2+1]*__expf(m1 - M);
            g_rowlse[b*Ln + i0 + tid] = M + __logf(S);
        }
        __threadfence();
        __syncthreads();
        if (tid == 0) atomicAdd(&g_barr3, 1u);
        return;
    }
    if (bid < 56) {
        // ---- p12 GEMM: 16 blocks, 4 col-subtiles sharing one h row-tile ----
        int pbi = bid - 40;             // 0..15
        int br = pbi >> 1, cq = pbi & 1;
        int st = tid >> 8;              // subtile 0..3
        int stid = tid & 255;
        int bc = cq*4 + st;
        const float* W    = (bc < 4) ? W1 : W2;
        const float* bias = (bc < 4) ? b1 : b2;
        float* dst        = (bc < 4) ? g_p1 : g_p2;
        int c0 = (bc & 3) * 32;
        int r0 = br * 64;
        float* hsh = smf;                         // 64k x 64row pitch 68
        float* wsh = smf + 4352 + st*2176;        // 32c x 64k pitch 68
        int tr = stid >> 4, tc = stid & 15;
        float a0[2] = {}, a1[2] = {}, a2[2] = {}, a3[2] = {};
        int srow = tid & 63, skq = tid >> 6;      // 0..15
        int swc = stid >> 3, swk8 = (stid & 7) * 8;
        for (int k0 = 0; k0 < HIDD; k0 += 64) {
            float4 v = *(const float4*)&g_hs[(size_t)(r0+srow)*HIDD + k0 + skq*4];
            int kb = skq*4;
            hsh[(kb+0)*68+srow]=v.x; hsh[(kb+1)*68+srow]=v.y;
            hsh[(kb+2)*68+srow]=v.z; hsh[(kb+3)*68+srow]=v.w;
            *(float4*)&wsh[swc*68 + swk8] =
                *(const float4*)&W[(size_t)(c0 + swc)*HIDD + k0 + swk8];
            *(float4*)&wsh[swc*68 + swk8 + 4] =
                *(const float4*)&W[(size_t)(c0 + swc)*HIDD + k0 + swk8 + 4];
            __syncthreads();
            #pragma unroll 8
            for (int k = 0; k < 64; k += 4) {
                float4 w0 = *(const float4*)&wsh[(tc*2  )*68 + k];
                float4 w1 = *(const float4*)&wsh[(tc*2+1)*68 + k];
                float4 h0 = *(const float4*)&hsh[(k+0)*68 + tr*4];
                float4 h1 = *(const float4*)&hsh[(k+1)*68 + tr*4];
                float4 h2 = *(const float4*)&hsh[(k+2)*68 + tr*4];
                float4 h3 = *(const float4*)&hsh[(k+3)*68 + tr*4];
                a0[0] += h0.x*w0.x + h1.x*w0.y + h2.x*w0.z + h3.x*w0.w;
                a1[0] += h0.y*w0.x + h1.y*w0.y + h2.y*w0.z + h3.y*w0.w;
                a2[0] += h0.z*w0.x + h1.z*w0.y + h2.z*w0.z + h3.z*w0.w;
                a3[0] += h0.w*w0.x + h1.w*w0.y + h2.w*w0.z + h3.w*w0.w;
                a0[1] += h0.x*w1.x + h1.x*w1.y + h2.x*w1.z + h3.x*w1.w;
                a1[1] += h0.y*w1.x + h1.y*w1.y + h2.y*w1.z + h3.y*w1.w;
                a2[1] += h0.z*w1.x + h1.z*w1.y + h2.z*w1.z + h3.z*w1.w;
                a3[1] += h0.w*w1.x + h1.w*w1.y + h2.w*w1.z + h3.w*w1.w;
            }
            __syncthreads();
        }
        int cc = c0 + tc*2;
        float2 bv = { bias[cc], bias[cc+1] };
        *(float2*)&dst[(r0 + tr*4 + 0)*RECD + cc] = make_float2(a0[0]+bv.x, a0[1]+bv.y);
        *(float2*)&dst[(r0 + tr*4 + 1)*RECD + cc] = make_float2(a1[0]+bv.x, a1[1]+bv.y);
        *(float2*)&dst[(r0 + tr*4 + 2)*RECD + cc] = make_float2(a2[0]+bv.x, a2[1]+bv.y);
        *(float2*)&dst[(r0 + tr*4 + 3)*RECD + cc] = make_float2(a3[0]+bv.x, a3[1]+bv.y);
        __threadfence();
        __syncthreads();
        if (tid == 0) atomicAdd(&g_barrPb[br], 1u);
        return;
    }
    // ---- uv: 64 blocks x 8 rows ----
    {
        __shared__ float pu[32], pv[32];
        int ub2 = bid - 56;
        int row = ub2*8 + (tid >> 7);
        int t128 = tid & 127;
        int l = row & 63;
        const float4* hc = (const float4*)&g_hs[(size_t)row*HIDD];
        const float4* W4 = (const float4*)Ws;
        float4 h0 = hc[t128];
        float4 wu0 = W4[t128], wv0 = W4[384 + t128];
        float au = h0.x*wu0.x + h0.y*wu0.y + h0.z*wu0.z + h0.w*wu0.w;
        float av = h0.x*wv0.x + h0.y*wv0.y + h0.z*wv0.z + h0.w*wv0.w;
        if (l > 0) {
            float4 hb = hc[t128 - 128];
            float4 wu = W4[128 + t128], wv = W4[512 + t128];
            au += hb.x*wu.x + hb.y*wu.y + hb.z*wu.z + hb.w*wu.w;
            av += hb.x*wv.x + hb.y*wv.y + hb.z*wv.z + hb.w*wv.w;
        }
        if (l < 63) {
            float4 hn = hc[t128 + 128];
            float4 wu = W4[256 + t128], wv = W4[640 + t128];
            au += hn.x*wu.x + hn.y*wu.y + hn.z*wu.z + hn.w*wu.w;
            av += hn.x*wv.x + hn.y*wv.y + hn.z*wv.z + hn.w*wv.w;
        }
        #pragma unroll
        for (int o = 16; o; o >>= 1) {
            au += __shfl_xor_sync(0xffffffffu, au, o);
            av += __shfl_xor_sync(0xffffffffu, av, o);
        }
        int warp = tid >> 5, lane = tid & 31;
        if (lane == 0) { pu[warp] = au; pv[warp] = av; }
        __syncthreads();
        if (t128 == 0) {
            int wb = (tid >> 7)*4;
            g_u[row] = pu[wb]+pu[wb+1]+pu[wb+2]+pu[wb+3];
            g_v[row] = pv[wb]+pv[wb+1]+pv[wb+2]+pv[wb+3];
        }
        __threadfence();
        __syncthreads();
        if (tid == 0) atomicAdd(&g_barrUb[ub2 >> 3], 1u);
    }
}

extern "C" void kernel_launch(void* const* d_in, const int* in_sizes, int n_in,
                              void* d_out, int out_size) {
    const int*   sents = (const int*)  d_in[0];
    const float* mask  = (const float*)d_in[1];
    const float* prior = (const float*)d_in[2];
    const int*   heads = (const int*)  d_in[3];
    const float* emb   = (const float*)d_in[4];
    const float* Wih_f = (const float*)d_in[5];
    const float* Whh_f = (const float*)d_in[6];
    const float* bih_f = (const float*)d_in[7];
    const float* bhh_f = (const float*)d_in[8];
    const float* Wih_b = (const float*)d_in[9];
    const float* Whh_b = (const float*)d_in[10];
    const float* bih_b = (const float*)d_in[11];
    const float* bhh_b = (const float*)d_in[12];
    const float* W1    = (const float*)d_in[13];
    const float* b1    = (const float*)d_in[14];
    const float* W2    = (const float*)d_in[15];
    const float* b2    = (const float*)d_in[16];
    const float* Ws    = (const float*)d_in[17];
    const float* bsv   = (const float*)d_in[18];
    float* out = (float*)d_out;
    (void)in_sizes; (void)n_in; (void)out_size;

    cudaFuncSetAttribute(k_lstm_all, cudaFuncAttributeMaxDynamicSharedMemorySize, 22656*4);
    cudaFuncSetAttribute(k_tail,     cudaFuncAttributeMaxDynamicSharedMemorySize, 16640*4);

    dim3 g1(8, 16, 2);
    k_emb_xw<<<g1, 256>>>(sents, mask, emb, Wih_f, bih_f, bhh_f, Wih_b, bih_b, bhh_b);
    k_lstm_all<<<128, 128, 22656*4>>>(Whh_f, Whh_b);
    k_tail<<<120, 1024, 16640*4>>>(bsv, heads, prior, Ws, W1, b1, W2, b2, out);
}

// round 16
// speedup vs baseline: 1.0477x; 1.0225x over previous
#include <cuda_runtime.h>
#include <math.h>

#define Bz 8
#define Ln 64
#define WL 32
#define EMBD 256
#define H2 256
#define HIDD 512
#define RECD 128
#define NEGV -1000000000.0f

__device__ float g_embeds[Bz*Ln*EMBD];
__device__ float g_xw[2*Bz*Ln*1024];
__device__ float g_hT[4*H2*Ln];          // [buf(2)][dir(2)][unit 256][n 64]
__device__ unsigned g_barr[16];          // lstm [dir][step]
__device__ unsigned g_barr2;             // embed->xw grid barrier
__device__ unsigned g_barr3;             // eis/scores->final arrivals
__device__ unsigned g_barrU;             // uv done (64 blocks)
__device__ unsigned g_barrP;             // p12 done (16 blocks)
__device__ float g_hs[Bz*Ln*HIDD];
__device__ float g_u[Bz*Ln];
__device__ float g_v[Bz*Ln];
__device__ float g_p1[Bz*Ln*RECD];
__device__ float g_p2[Bz*Ln*RECD];
__device__ float g_s[Bz*Ln*Ln];
__device__ float g_rowlse[Bz*Ln];
__device__ float g_logZ[Bz];

__device__ __forceinline__ float fsig(float x) {
    return __fdividef(1.0f, 1.0f + __expf(-x));
}

// K1 (fused): embed (2 rows/block) -> grid barrier (256) -> xW GEMM 64x64 tile.
__global__ void k_emb_xw(const int* __restrict__ sents, const float* __restrict__ mask,
                         const float* __restrict__ emb,
                         const float* __restrict__ Wf, const float* __restrict__ bif,
                         const float* __restrict__ bhf,
                         const float* __restrict__ Wb, const float* __restrict__ bib,
                         const float* __restrict__ bhb) {
    int lin = blockIdx.x + blockIdx.y*8 + blockIdx.z*128;   // 0..255
    int tid = threadIdx.x;
    __shared__ __align__(16) float Ash[64*68];
    __shared__ __align__(16) float Wsh[64*68];
    __shared__ int sw[WL]; __shared__ float sm[WL]; __shared__ float sden;
    #pragma unroll
    for (int r = 0; r < 2; r++) {
        int row = lin*2 + r;
        if (tid < WL) { sw[tid] = sents[row*WL + tid]; sm[tid] = mask[row*WL + tid]; }
        __syncthreads();
        if (tid == 0) {
            float e = 0.f;
            for (int w = 0; w < WL; w++) e += sm[w];
            sden = e + (e == 0.0f ? 1.0f : 0.0f);
        }
        __syncthreads();
        float acc = 0.f;
        #pragma unroll 8
        for (int w = 0; w < WL; w++) acc += emb[(size_t)sw[w]*EMBD + tid] * sm[w];
        g_embeds[row*EMBD + tid] = acc / sden;
        __syncthreads();
    }
    __threadfence();
    if (tid == 0) {
        unsigned c = atomicAdd(&g_barr2, 1u) + 1u;
        if (c < 256u) {
            volatile unsigned* p = &g_barr2;
            while (*p < 256u) { }
        }
    }
    __syncthreads();
    int dir = blockIdx.z;
    const float* W  = dir ? Wb  : Wf;
    const float* bi = dir ? bib : bif;
    const float* bh = dir ? bhb : bhf;
    int r0 = blockIdx.x * 64, g0 = blockIdx.y * 64;
    int ri = tid & 15, gi = tid >> 4;
    float acc[4][4] = {};
    for (int e0 = 0; e0 < EMBD; e0 += 64) {
        #pragma unroll 4
        for (int q = 0; q < 16; q++) {
            int li = tid + q*256;
            int xx = li >> 6, ee = li & 63;
            Ash[ee*68 + xx] = __ldcg(&g_embeds[(r0+xx)*EMBD + e0 + ee]);
            Wsh[ee*68 + xx] = W[(g0+xx)*EMBD + e0 + ee];
        }
        __syncthreads();
        #pragma unroll 8
        for (int e = 0; e < 64; e++) {
            float4 av = *(const float4*)&Ash[e*68 + ri*4];
            float4 wv = *(const float4*)&Wsh[e*68 + gi*4];
            float aa[4] = {av.x, av.y, av.z, av.w};
            float ww[4] = {wv.x, wv.y, wv.z, wv.w};
            #pragma unroll
            for (int a = 0; a < 4; a++)
                #pragma unroll
                for (int g = 0; g < 4; g++) acc[a][g] += aa[a]*ww[g];
        }
        __syncthreads();
    }
    #pragma unroll
    for (int a = 0; a < 4; a++)
        #pragma unroll
        for (int g = 0; g < 4; g++) {
            int row = r0 + ri*4 + a, gg = g0 + gi*4 + g;
            g_xw[((size_t)dir*Bz*Ln + row)*1024 + gg] = acc[a][g] + bi[gg] + bh[gg];
        }
}

// K2: persistent LSTM — all 8 steps in one kernel.
__global__ void k_lstm_all(const float* __restrict__ Whh_f, const float* __restrict__ Whh_b) {
    extern __shared__ float smem[];
    float* wsh = smem;                  // [gc 16][e 256] pitch 260
    float* hsh = smem + 4160;           // [e 256][n 64] pitch 68
    float* gsh = smem + 4160 + 17408;   // [gc 16][n 64] pitch 68
    int bx = blockIdx.x;
    int dir = bx >> 6, ub = bx & 63, u0 = ub*4;
    const float* Whh = dir ? Whh_b : Whh_f;
    int tid = threadIdx.x;

    #pragma unroll 8
    for (int q = 0; q < 32; q++) {
        int li = tid + q*128;
        int gc = li >> 8, e = li & 255;
        int ul = gc >> 2, gate = gc & 3;
        wsh[gc*260 + e] = Whh[(gate*H2 + u0 + ul)*H2 + e];
    }
    int ng = tid >> 3, gg = tid & 7;
    int n_c = tid & 63, ul_c = tid >> 6;
    float c0 = 0.f, c1 = 0.f;
    __syncthreads();

    for (int s = 0; s < Bz; s++) {
        int t = dir ? (Bz-1-s) : s;
        const float* xb = &g_xw[((size_t)(dir*Bz*Ln + t*Ln + n_c))*1024 + u0 + ul_c];
        float xw0[4], xw1[4];
        #pragma unroll
        for (int g = 0; g < 4; g++) { xw0[g] = xb[g*256]; xw1[g] = xb[g*256 + 2]; }

        float a00=0.f,a01=0.f,a10=0.f,a11=0.f,a20=0.f,a21=0.f,a30=0.f,a31=0.f;
        if (s > 0) {
            const float* hp = &g_hT[((s&1)*2 + dir)*H2*Ln];
            #pragma unroll 8
            for (int q = 0; q < 32; q++) {
                int idx = (tid + q*128)*4;
                int e = idx >> 6, n = idx & 63;
                float4 hv = __ldcg((const float4*)(hp + idx));
                *(float4*)&hsh[e*68 + n] = hv;
            }
            __syncthreads();
            #pragma unroll 4
            for (int e4 = 0; e4 < H2; e4 += 4) {
                float4 w0 = *(const float4*)&wsh[(gg*2  )*260 + e4];
                float4 w1 = *(const float4*)&wsh[(gg*2+1)*260 + e4];
                float wa[4] = {w0.x, w0.y, w0.z, w0.w};
                float wb[4] = {w1.x, w1.y, w1.z, w1.w};
                #pragma unroll
                for (int k = 0; k < 4; k++) {
                    float4 hv = *(const float4*)&hsh[(e4+k)*68 + ng*4];
                    a00 += hv.x*wa[k]; a01 += hv.x*wb[k];
                    a10 += hv.y*wa[k]; a11 += hv.y*wb[k];
                    a20 += hv.z*wa[k]; a21 += hv.z*wb[k];
                    a30 += hv.w*wa[k]; a31 += hv.w*wb[k];
                }
            }
        } else {
            __syncthreads();
        }
        gsh[(gg*2  )*68 + ng*4 + 0] = a00; gsh[(gg*2+1)*68 + ng*4 + 0] = a01;
        gsh[(gg*2  )*68 + ng*4 + 1] = a10; gsh[(gg*2+1)*68 + ng*4 + 1] = a11;
        gsh[(gg*2  )*68 + ng*4 + 2] = a20; gsh[(gg*2+1)*68 + ng*4 + 2] = a21;
        gsh[(gg*2  )*68 + ng*4 + 3] = a30; gsh[(gg*2+1)*68 + ng*4 + 3] = a31;
        __syncthreads();
        {
            float iv = gsh[(ul_c*4+0)*68 + n_c] + xw0[0];
            float fv = gsh[(ul_c*4+1)*68 + n_c] + xw0[1];
            float gv = gsh[(ul_c*4+2)*68 + n_c] + xw0[2];
            float ov = gsh[(ul_c*4+3)*68 + n_c] + xw0[3];
            c0 = fsig(fv)*c0 + fsig(iv)*__tanhf(gv);
            float h0 = fsig(ov)*__tanhf(c0);
            int ul2 = ul_c + 2;
            float iv1 = gsh[(ul2*4+0)*68 + n_c] + xw1[0];
            float fv1 = gsh[(ul2*4+1)*68 + n_c] + xw1[1];
            float gv1 = gsh[(ul2*4+2)*68 + n_c] + xw1[2];
            float ov1 = gsh[(ul2*4+3)*68 + n_c] + xw1[3];
            c1 = fsig(fv1)*c1 + fsig(iv1)*__tanhf(gv1);
            float h1 = fsig(ov1)*__tanhf(c1);
            int wbuf = (((s+1)&1)*2 + dir)*H2*Ln;
            __stcg(&g_hT[wbuf + (u0+ul_c )*Ln + n_c], h0);
            __stcg(&g_hT[wbuf + (u0+ul2  )*Ln + n_c], h1);
            g_hs[((size_t)t*Ln + n_c)*HIDD + dir*H2 + u0 + ul_c] = h0;
            g_hs[((size_t)t*Ln + n_c)*HIDD + dir*H2 + u0 + ul2 ] = h1;
        }
        if (s < Bz-1) {
            __threadfence();
            __syncthreads();
            if (tid == 0) {
                unsigned c = atomicAdd(&g_barr[dir*8 + s], 1u) + 1u;
                if (c < 64u) {
                    volatile unsigned* p = &g_barr[dir*8 + s];
                    while (*p < 64u) { }
                }
            }
            __syncthreads();
        }
    }
}

// Eisner width-step: NQ = ceil(w/16) known at compile time.
template<int NQ>
__device__ __forceinline__ void eis_step(
    float* __restrict__ Cr, float* __restrict__ Cl,
    float* __restrict__ Ir, float* __restrict__ Il,
    const float* __restrict__ ush, const float* __restrict__ vsh,
    int w, int spans, int grp, int l16)
{
    bool valid = grp < spans;
    int i = valid ? grp : 0, jn = i + w;
    float t_in[NQ], t_cr[NQ], t_cl[NQ];
    float m_in = -INFINITY, m_cr = -INFINITY, m_cl = -INFINITY;
    #pragma unroll
    for (int q = 0; q < NQ; q++) {
        int o = l16 + q*16;
        t_in[q] = -INFINITY; t_cr[q] = -INFINITY; t_cl[q] = -INFINITY;
        if (valid && o < w) {
            int k = i + o;
            t_in[q] = Cr[i*65 + k] + Cl[(k+1)*65 + jn];
            if (o < w - 1) {
                int k2 = k + 1;
                t_cr[q] = Ir[i*65 + k2] + Cr[k2*65 + jn];
                t_cl[q] = Cl[i*65 + k2] + Il[k2*65 + jn];
            }
        }
        m_in = fmaxf(m_in, t_in[q]);
        m_cr = fmaxf(m_cr, t_cr[q]);
        m_cl = fmaxf(m_cl, t_cl[q]);
    }
    #pragma unroll
    for (int o = 8; o; o >>= 1) {
        m_in = fmaxf(m_in, __shfl_xor_sync(0xffffffffu, m_in, o));
        m_cr = fmaxf(m_cr, __shfl_xor_sync(0xffffffffu, m_cr, o));
        m_cl = fmaxf(m_cl, __shfl_xor_sync(0xffffffffu, m_cl, o));
    }
    float ms_in = fmaxf(m_in, -1e30f);
    float ms_cr = fmaxf(m_cr, -1e30f);
    float ms_cl = fmaxf(m_cl, -1e30f);
    float s_in = 0.f, s_cr = 0.f, s_cl = 0.f;
    #pragma unroll
    for (int q = 0; q < NQ; q++) {
        s_in += __expf(t_in[q] - ms_in);
        s_cr += __expf(t_cr[q] - ms_cr);
        s_cl += __expf(t_cl[q] - ms_cl);
    }
    #pragma unroll
    for (int o = 8; o; o >>= 1) {
        s_in += __shfl_xor_sync(0xffffffffu, s_in, o);
        s_cr += __shfl_xor_sync(0xffffffffu, s_cr, o);
        s_cl += __shfl_xor_sync(0xffffffffu, s_cl, o);
    }
    if (valid && l16 == 0) {
        float inc = ms_in + __logf(s_in);
        float irv = inc + ush[i]  + vsh[jn];
        float ilv = inc + ush[jn] + vsh[i];
        Ir[i*65 + jn] = irv;
        Il[i*65 + jn] = ilv;
        float lcr = ms_cr + __logf(s_cr);
        float M = fmaxf(lcr, irv);
        Cr[i*65 + jn] = M + __logf(__expf(lcr - M) + __expf(irv - M));
        float lcl = ms_cl + __logf(s_cl);
        float Ml = fmaxf(lcl, ilv);
        Cl[i*65 + jn] = Ml + __logf(__expf(lcl - Ml) + __expf(ilv - Ml));
    }
}

// K3 (tail): blocks 0..7 eisner(+final in blk0); 8..39 scores; 40..55 p12;
// 56..119 uv. Spin deps: uv->eisner (g_barrU), p12->scores (g_barrP).
// Eisner uses shrinking barriers: 1024 thr for w<=32, 512 for w<=48, 256 after.
__global__ void __launch_bounds__(1024, 1)
k_tail(const float* __restrict__ bs, const int* __restrict__ heads,
       const float* __restrict__ prior, const float* __restrict__ Ws,
       const float* __restrict__ W1, const float* __restrict__ b1,
       const float* __restrict__ W2, const float* __restrict__ b2,
       float* __restrict__ out) {
    extern __shared__ float smf[];
    int tid = threadIdx.x;
    int bid = blockIdx.x;
    if (bid < 8) {
        // ---- Eisner ----
        float* Cr = smf;         float* Cl = smf + 4160;
        float* Ir = smf + 8320;  float* Il = smf + 12480;
        __shared__ float ush[64], vsh[64];
        int b = bid;
        for (int idx = tid; idx < 4160; idx += 1024) {
            int i = idx / 65, jj = idx % 65;
            float dv = (jj < 64 && i == jj) ? 0.0f : NEGV;
            Cr[idx] = dv; Cl[idx] = dv; Ir[idx] = NEGV; Il[idx] = NEGV;
        }
        if (tid == 0) {
            volatile unsigned* p = &g_barrU;
            while (*p < 64u) { }
        }
        __syncthreads();
        if (tid < 64) {
            ush[tid] = __ldcg(&g_u[b*Ln + tid]) + bs[0];
            vsh[tid] = __ldcg(&g_v[b*Ln + tid]);
        }
        __syncthreads();
        int grp = tid >> 4, l16 = tid & 15, wrp = tid >> 5;
        // band 1: w 1..16 (NQ=1), all 32 warps
        for (int w = 1; w <= 16; w++) {
            int spans = Ln - w;
            if (wrp*2 < spans)
                eis_step<1>(Cr, Cl, Ir, Il, ush, vsh, w, spans, grp, l16);
            __syncthreads();
        }
        // band 2: w 17..32 (NQ=2), all 32 warps
        for (int w = 17; w <= 32; w++) {
            int spans = Ln - w;
            if (wrp*2 < spans)
                eis_step<2>(Cr, Cl, Ir, Il, ush, vsh, w, spans, grp, l16);
            __syncthreads();
        }
        // band 3: w 33..48 (NQ=3), warps 0..15 only (spans <= 31)
        if (wrp < 16) {
            for (int w = 33; w <= 48; w++) {
                int spans = Ln - w;
                if (wrp*2 < spans)
                    eis_step<3>(Cr, Cl, Ir, Il, ush, vsh, w, spans, grp, l16);
                asm volatile("bar.sync 1, 512;" ::: "memory");
            }
            // band 4: w 49..63 (NQ=4), warps 0..7 only (spans <= 15)
            if (wrp < 8) {
                for (int w = 49; w <= 63; w++) {
                    int spans = Ln - w;
                    if (wrp*2 < spans)
                        eis_step<4>(Cr, Cl, Ir, Il, ush, vsh, w, spans, grp, l16);
                    asm volatile("bar.sync 2, 256;" ::: "memory");
                }
            }
        }
        __syncthreads();   // all 32 warps rejoin
        if (tid == 0) g_logZ[b] = Cr[Ln - 1];
        __threadfence();
        __syncthreads();
        if (bid == 0) {
            if (tid == 0) {
                unsigned c = atomicAdd(&g_barr3, 1u) + 1u;
                if (c < 40u) {
                    volatile unsigned* p = &g_barr3;
                    while (*p < 40u) { }
                }
            }
            __syncthreads();
            if (tid < 256) {
                int warp = tid >> 5, lane = tid & 31;
                __shared__ float sb[8];
                int b2 = warp;
                float bsv = bs[0];
                int m1 = lane + 1, m2 = lane + 33;
                float v1, v2;
                {
                    int hd = heads[b2*Ln + m1];
                    v1 = __ldcg(&g_u[b2*Ln + hd]) + __ldcg(&g_v[b2*Ln + m1]) + bsv
                       + __ldcg(&g_s[((size_t)b2*Ln + hd)*Ln + m1])
                       - __ldcg(&g_rowlse[b2*Ln + hd])
                       + prior[((size_t)b2*Ln + hd)*Ln + m1] * (1.0f/64.0f);
                }
                if (m2 < Ln) {
                    int hd = heads[b2*Ln + m2];
                    v2 = __ldcg(&g_u[b2*Ln + hd]) + __ldcg(&g_v[b2*Ln + m2]) + bsv
                       + __ldcg(&g_s[((size_t)b2*Ln + hd)*Ln + m2])
                       - __ldcg(&g_rowlse[b2*Ln + hd])
                       + prior[((size_t)b2*Ln + hd)*Ln + m2] * (1.0f/64.0f);
                } else v2 = -INFINITY;
                float mx = fmaxf(v1, v2);
                #pragma unroll
                for (int o = 16; o; o >>= 1) mx = fmaxf(mx, __shfl_xor_sync(0xffffffffu, mx, o));
                float sum = __expf(v1 - mx) + __expf(v2 - mx);
                #pragma unroll
                for (int o = 16; o; o >>= 1) sum += __shfl_xor_sync(0xffffffffu, sum, o);
                if (lane == 0) sb[b2] = (mx + __logf(sum)) - __ldcg(&g_logZ[b2]);
                __syncthreads();
                if (tid == 0) {
                    float t = 0.f;
                    for (int q = 0; q < 8; q++) t += sb[q];
                    out[0] = -t * (1.0f/8.0f);
                    for (int q = 0; q < 16; q++) g_barr[q] = 0u;
                    g_barr2 = 0u; g_barr3 = 0u; g_barrU = 0u; g_barrP = 0u;
                }
            }
        } else {
            if (tid == 0) atomicAdd(&g_barr3, 1u);
        }
        return;
    }
    if (bid < 40) {
        // ---- scores (waits for p12) ----
        int sb2 = bid - 8;
        int b = sb2 >> 2, i0 = (sb2 & 3) * 16;
        float* p1sh = smf;              // 16 x 132
        float* p2sh = smf + 16*132;     // 64 x 132
        __shared__ float mm[32], ss[32];
        if (tid == 0) {
            volatile unsigned* p = &g_barrP;
            while (*p < 16u) { }
        }
        __syncthreads();
        if (tid < 512) {
            int rr = tid >> 5, e4 = tid & 31;
            *(float4*)&p1sh[rr*132 + e4*4] =
                __ldcg((const float4*)&g_p1[(b*Ln + i0 + rr)*RECD + e4*4]);
        }
        #pragma unroll
        for (int q = 0; q < 2; q++) {
            int li = tid + q*1024;
            int rr = li >> 5, e4 = li & 31;
            *(float4*)&p2sh[rr*132 + e4*4] =
                __ldcg((const float4*)&g_p2[(b*Ln + rr)*RECD + e4*4]);
        }
        __syncthreads();
        int i_l = tid >> 6, j = tid & 63;
        float dot = 0.f;
        #pragma unroll 8
        for (int e4 = 0; e4 < 32; e4++) {
            float4 a = *(const float4*)&p1sh[i_l*132 + e4*4];
            float4 bv = *(const float4*)&p2sh[j*132 + e4*4];
            dot += a.x*bv.x + a.y*bv.y + a.z*bv.z + a.w*bv.w;
        }
        int i = i0 + i_l;
        g_s[((size_t)b*Ln + i)*Ln + j] = dot;
        float m = dot;
        #pragma unroll
        for (int o = 16; o; o >>= 1) m = fmaxf(m, __shfl_xor_sync(0xffffffffu, m, o));
        float sum = __expf(dot - m);
        #pragma unroll
        for (int o = 16; o; o >>= 1) sum += __shfl_xor_sync(0xffffffffu, sum, o);
        int warp = tid >> 5, lane = tid & 31;
        if (lane == 0) { mm[warp] = m; ss[warp] = sum; }
        __syncthreads();
        if (tid < 16) {
            float m0 = mm[tid*2], m1 = mm[tid*2+1];
            float M = fmaxf(m0, m1);
            float S = ss[tid*2]*__expf(m0 - M) + ss[tid*2+1]*__expf(m1 - M);
            g_rowlse[b*Ln + i0 + tid] = M + __logf(S);
        }
        __threadfence();
        __syncthreads();
        if (tid == 0) atomicAdd(&g_barr3, 1u);
        return;
    }
    if (bid < 56) {
        // ---- p12 GEMM: 16 blocks, 4 col-subtiles sharing one h row-tile ----
        int pbi = bid - 40;             // 0..15
        int br = pbi >> 1, cq = pbi & 1;
        int st = tid >> 8;              // subtile 0..3
        int stid = tid & 255;
        int bc = cq*4 + st;
        const float* W    = (bc < 4) ? W1 : W2;
        const float* bias = (bc < 4) ? b1 : b2;
        float* dst        = (bc < 4) ? g_p1 : g_p2;
        int c0 = (bc & 3) * 32;
        int r0 = br * 64;
        float* hsh = smf;                         // 64k x 64row pitch 68
        float* wsh = smf + 4352 + st*2176;        // 32c x 64k pitch 68
        int tr = stid >> 4, tc = stid & 15;
        float a0[2] = {}, a1[2] = {}, a2[2] = {}, a3[2] = {};
        int srow = tid & 63, skq = tid >> 6;      // 0..15
        int swc = stid >> 3, swk8 = (stid & 7) * 8;
        for (int k0 = 0; k0 < HIDD; k0 += 64) {
            float4 v = *(const float4*)&g_hs[(size_t)(r0+srow)*HIDD + k0 + skq*4];
            int kb = skq*4;
            hsh[(kb+0)*68+srow]=v.x; hsh[(kb+1)*68+srow]=v.y;
            hsh[(kb+2)*68+srow]=v.z; hsh[(kb+3)*68+srow]=v.w;
            *(float4*)&wsh[swc*68 + swk8] =
                *(const float4*)&W[(size_t)(c0 + swc)*HIDD + k0 + swk8];
            *(float4*)&wsh[swc*68 + swk8 + 4] =
                *(const float4*)&W[(size_t)(c0 + swc)*HIDD + k0 + swk8 + 4];
            __syncthreads();
            #pragma unroll 8
            for (int k = 0; k < 64; k += 4) {
                float4 w0 = *(const float4*)&wsh[(tc*2  )*68 + k];
                float4 w1 = *(const float4*)&wsh[(tc*2+1)*68 + k];
                float4 h0 = *(const float4*)&hsh[(k+0)*68 + tr*4];
                float4 h1 = *(const float4*)&hsh[(k+1)*68 + tr*4];
                float4 h2 = *(const float4*)&hsh[(k+2)*68 + tr*4];
                float4 h3 = *(const float4*)&hsh[(k+3)*68 + tr*4];
                a0[0] += h0.x*w0.x + h1.x*w0.y + h2.x*w0.z + h3.x*w0.w;
                a1[0] += h0.y*w0.x + h1.y*w0.y + h2.y*w0.z + h3.y*w0.w;
                a2[0] += h0.z*w0.x + h1.z*w0.y + h2.z*w0.z + h3.z*w0.w;
                a3[0] += h0.w*w0.x + h1.w*w0.y + h2.w*w0.z + h3.w*w0.w;
                a0[1] += h0.x*w1.x + h1.x*w1.y + h2.x*w1.z + h3.x*w1.w;
                a1[1] += h0.y*w1.x + h1.y*w1.y + h2.y*w1.z + h3.y*w1.w;
                a2[1] += h0.z*w1.x + h1.z*w1.y + h2.z*w1.z + h3.z*w1.w;
                a3[1] += h0.w*w1.x + h1.w*w1.y + h2.w*w1.z + h3.w*w1.w;
            }
            __syncthreads();
        }
        int cc = c0 + tc*2;
        float2 bv = { bias[cc], bias[cc+1] };
        *(float2*)&dst[(r0 + tr*4 + 0)*RECD + cc] = make_float2(a0[0]+bv.x, a0[1]+bv.y);
        *(float2*)&dst[(r0 + tr*4 + 1)*RECD + cc] = make_float2(a1[0]+bv.x, a1[1]+bv.y);
        *(float2*)&dst[(r0 + tr*4 + 2)*RECD + cc] = make_float2(a2[0]+bv.x, a2[1]+bv.y);
        *(float2*)&dst[(r0 + tr*4 + 3)*RECD + cc] = make_float2(a3[0]+bv.x, a3[1]+bv.y);
        __threadfence();
        __syncthreads();
        if (tid == 0) atomicAdd(&g_barrP, 1u);
        return;
    }
    // ---- uv: 64 blocks x 8 rows ----
    {
        __shared__ float pu[32], pv[32];
        int row = (bid - 56)*8 + (tid >> 7);
        int t128 = tid & 127;
        int l = row & 63;
        const float4* hc = (const float4*)&g_hs[(size_t)row*HIDD];
        const float4* W4 = (const float4*)Ws;
        float4 h0 = hc[t128];
        float4 wu0 = W4[t128], wv0 = W4[384 + t128];
        float au = h0.x*wu0.x + h0.y*wu0.y + h0.z*wu0.z + h0.w*wu0.w;
        float av = h0.x*wv0.x + h0.y*wv0.y + h0.z*wv0.z + h0.w*wv0.w;
        if (l > 0) {
            float4 hb = hc[t128 - 128];
            float4 wu = W4[128 + t128], wv = W4[512 + t128];
            au += hb.x*wu.x + hb.y*wu.y + hb.z*wu.z + hb.w*wu.w;
            av += hb.x*wv.x + hb.y*wv.y + hb.z*wv.z + hb.w*wv.w;
        }
        if (l < 63) {
            float4 hn = hc[t128 + 128];
            float4 wu = W4[256 + t128], wv = W4[640 + t128];
            au += hn.x*wu.x + hn.y*wu.y + hn.z*wu.z + hn.w*wu.w;
            av += hn.x*wv.x + hn.y*wv.y + hn.z*wv.z + hn.w*wv.w;
        }
        #pragma unroll
        for (int o = 16; o; o >>= 1) {
            au += __shfl_xor_sync(0xffffffffu, au, o);
            av += __shfl_xor_sync(0xffffffffu, av, o);
        }
        int warp = tid >> 5, lane = tid & 31;
        if (lane == 0) { pu[warp] = au; pv[warp] = av; }
        __syncthreads();
        if (t128 == 0) {
            int wb = (tid >> 7)*4;
            g_u[row] = pu[wb]+pu[wb+1]+pu[wb+2]+pu[wb+3];
            g_v[row] = pv[wb]+pv[wb+1]+pv[wb+2]+pv[wb+3];
        }
        __threadfence();
        __syncthreads();
        if (tid == 0) atomicAdd(&g_barrU, 1u);
    }
}

extern "C" void kernel_launch(void* const* d_in, const int* in_sizes, int n_in,
                              void* d_out, int out_size) {
    const int*   sents = (const int*)  d_in[0];
    const float* mask  = (const float*)d_in[1];
    const float* prior = (const float*)d_in[2];
    const int*   heads = (const int*)  d_in[3];
    const float* emb   = (const float*)d_in[4];
    const float* Wih_f = (const float*)d_in[5];
    const float* Whh_f = (const float*)d_in[6];
    const float* bih_f = (const float*)d_in[7];
    const float* bhh_f = (const float*)d_in[8];
    const float* Wih_b = (const float*)d_in[9];
    const float* Whh_b = (const float*)d_in[10];
    const float* bih_b = (const float*)d_in[11];
    const float* bhh_b = (const float*)d_in[12];
    const float* W1    = (const float*)d_in[13];
    const float* b1    = (const float*)d_in[14];
    const float* W2    = (const float*)d_in[15];
    const float* b2    = (const float*)d_in[16];
    const float* Ws    = (const float*)d_in[17];
    const float* bsv   = (const float*)d_in[18];
    float* out = (float*)d_out;
    (void)in_sizes; (void)n_in; (void)out_size;

    cudaFuncSetAttribute(k_lstm_all, cudaFuncAttributeMaxDynamicSharedMemorySize, 22656*4);
    cudaFuncSetAttribute(k_tail,     cudaFuncAttributeMaxDynamicSharedMemorySize, 16640*4);

    dim3 g1(8, 16, 2);
    k_emb_xw<<<g1, 256>>>(sents, mask, emb, Wih_f, bih_f, bhh_f, Wih_b, bih_b, bhh_b);
    k_lstm_all<<<128, 128, 22656*4>>>(Whh_f, Whh_b);
    k_tail<<<120, 1024, 16640*4>>>(bsv, heads, prior, Ws, W1, b1, W2, b2, out);
}

// round 17
// speedup vs baseline: 1.0504x; 1.0026x over previous
#include <cuda_runtime.h>
#include <math.h>

#define Bz 8
#define Ln 64
#define WL 32
#define EMBD 256
#define H2 256
#define HIDD 512
#define RECD 128
#define NEGV -1000000000.0f

__device__ float g_embeds[Bz*Ln*EMBD];
__device__ float g_xw[2*Bz*Ln*1024];
__device__ float g_hT[4*H2*Ln];          // [buf(2)][dir(2)][unit 256][n 64]
__device__ unsigned g_barr[16];          // lstm [dir][step]
__device__ unsigned g_barr2;             // embed->xw grid barrier
__device__ unsigned g_barr3;             // eis/scores->final arrivals
__device__ unsigned g_barrU;             // uv done (64 blocks)
__device__ unsigned g_barrP;             // p12 done (16 blocks)
__device__ float g_hs[Bz*Ln*HIDD];
__device__ float g_u[Bz*Ln];
__device__ float g_v[Bz*Ln];
__device__ float g_p1[Bz*Ln*RECD];
__device__ float g_p2[Bz*Ln*RECD];
__device__ float g_s[Bz*Ln*Ln];
__device__ float g_rowlse[Bz*Ln];
__device__ float g_logZ[Bz];

__device__ __forceinline__ float fsig(float x) {
    return __fdividef(1.0f, 1.0f + __expf(-x));
}

// K1 (fused): embed (2 rows/block) -> grid barrier (256) -> xW GEMM 64x64 tile.
__global__ void k_emb_xw(const int* __restrict__ sents, const float* __restrict__ mask,
                         const float* __restrict__ emb,
                         const float* __restrict__ Wf, const float* __restrict__ bif,
                         const float* __restrict__ bhf,
                         const float* __restrict__ Wb, const float* __restrict__ bib,
                         const float* __restrict__ bhb) {
    int lin = blockIdx.x + blockIdx.y*8 + blockIdx.z*128;   // 0..255
    int tid = threadIdx.x;
    __shared__ __align__(16) float Ash[64*68];
    __shared__ __align__(16) float Wsh[64*68];
    __shared__ int sw[WL]; __shared__ float sm[WL]; __shared__ float sden;
    #pragma unroll
    for (int r = 0; r < 2; r++) {
        int row = lin*2 + r;
        if (tid < WL) { sw[tid] = sents[row*WL + tid]; sm[tid] = mask[row*WL + tid]; }
        __syncthreads();
        if (tid == 0) {
            float e = 0.f;
            for (int w = 0; w < WL; w++) e += sm[w];
            sden = e + (e == 0.0f ? 1.0f : 0.0f);
        }
        __syncthreads();
        float acc = 0.f;
        #pragma unroll 8
        for (int w = 0; w < WL; w++) acc += emb[(size_t)sw[w]*EMBD + tid] * sm[w];
        g_embeds[row*EMBD + tid] = acc / sden;
        __syncthreads();
    }
    __threadfence();
    if (tid == 0) {
        unsigned c = atomicAdd(&g_barr2, 1u) + 1u;
        if (c < 256u) {
            volatile unsigned* p = &g_barr2;
            while (*p < 256u) { }
        }
    }
    __syncthreads();
    int dir = blockIdx.z;
    const float* W  = dir ? Wb  : Wf;
    const float* bi = dir ? bib : bif;
    const float* bh = dir ? bhb : bhf;
    int r0 = blockIdx.x * 64, g0 = blockIdx.y * 64;
    int ri = tid & 15, gi = tid >> 4;
    float acc[4][4] = {};
    for (int e0 = 0; e0 < EMBD; e0 += 64) {
        #pragma unroll 4
        for (int q = 0; q < 16; q++) {
            int li = tid + q*256;
            int xx = li >> 6, ee = li & 63;
            Ash[ee*68 + xx] = __ldcg(&g_embeds[(r0+xx)*EMBD + e0 + ee]);
            Wsh[ee*68 + xx] = W[(g0+xx)*EMBD + e0 + ee];
        }
        __syncthreads();
        #pragma unroll 8
        for (int e = 0; e < 64; e++) {
            float4 av = *(const float4*)&Ash[e*68 + ri*4];
            float4 wv = *(const float4*)&Wsh[e*68 + gi*4];
            float aa[4] = {av.x, av.y, av.z, av.w};
            float ww[4] = {wv.x, wv.y, wv.z, wv.w};
            #pragma unroll
            for (int a = 0; a < 4; a++)
                #pragma unroll
                for (int g = 0; g < 4; g++) acc[a][g] += aa[a]*ww[g];
        }
        __syncthreads();
    }
    #pragma unroll
    for (int a = 0; a < 4; a++)
        #pragma unroll
        for (int g = 0; g < 4; g++) {
            int row = r0 + ri*4 + a, gg = g0 + gi*4 + g;
            g_xw[((size_t)dir*Bz*Ln + row)*1024 + gg] = acc[a][g] + bi[gg] + bh[gg];
        }
}

// K2: persistent LSTM — all 8 steps in one kernel.
__global__ void k_lstm_all(const float* __restrict__ Whh_f, const float* __restrict__ Whh_b) {
    extern __shared__ float smem[];
    float* wsh = smem;                  // [gc 16][e 256] pitch 260
    float* hsh = smem + 4160;           // [e 256][n 64] pitch 68
    float* gsh = smem + 4160 + 17408;   // [gc 16][n 64] pitch 68
    int bx = blockIdx.x;
    int dir = bx >> 6, ub = bx & 63, u0 = ub*4;
    const float* Whh = dir ? Whh_b : Whh_f;
    int tid = threadIdx.x;

    #pragma unroll 8
    for (int q = 0; q < 32; q++) {
        int li = tid + q*128;
        int gc = li >> 8, e = li & 255;
        int ul = gc >> 2, gate = gc & 3;
        wsh[gc*260 + e] = Whh[(gate*H2 + u0 + ul)*H2 + e];
    }
    int ng = tid >> 3, gg = tid & 7;
    int n_c = tid & 63, ul_c = tid >> 6;
    float c0 = 0.f, c1 = 0.f;
    __syncthreads();

    for (int s = 0; s < Bz; s++) {
        int t = dir ? (Bz-1-s) : s;
        const float* xb = &g_xw[((size_t)(dir*Bz*Ln + t*Ln + n_c))*1024 + u0 + ul_c];
        float xw0[4], xw1[4];
        #pragma unroll
        for (int g = 0; g < 4; g++) { xw0[g] = xb[g*256]; xw1[g] = xb[g*256 + 2]; }

        float a00=0.f,a01=0.f,a10=0.f,a11=0.f,a20=0.f,a21=0.f,a30=0.f,a31=0.f;
        if (s > 0) {
            const float* hp = &g_hT[((s&1)*2 + dir)*H2*Ln];
            #pragma unroll 8
            for (int q = 0; q < 32; q++) {
                int idx = (tid + q*128)*4;
                int e = idx >> 6, n = idx & 63;
                float4 hv = __ldcg((const float4*)(hp + idx));
                *(float4*)&hsh[e*68 + n] = hv;
            }
            __syncthreads();
            #pragma unroll 4
            for (int e4 = 0; e4 < H2; e4 += 4) {
                float4 w0 = *(const float4*)&wsh[(gg*2  )*260 + e4];
                float4 w1 = *(const float4*)&wsh[(gg*2+1)*260 + e4];
                float wa[4] = {w0.x, w0.y, w0.z, w0.w};
                float wb[4] = {w1.x, w1.y, w1.z, w1.w};
                #pragma unroll
                for (int k = 0; k < 4; k++) {
                    float4 hv = *(const float4*)&hsh[(e4+k)*68 + ng*4];
                    a00 += hv.x*wa[k]; a01 += hv.x*wb[k];
                    a10 += hv.y*wa[k]; a11 += hv.y*wb[k];
                    a20 += hv.z*wa[k]; a21 += hv.z*wb[k];
                    a30 += hv.w*wa[k]; a31 += hv.w*wb[k];
                }
            }
        } else {
            __syncthreads();
        }
        gsh[(gg*2  )*68 + ng*4 + 0] = a00; gsh[(gg*2+1)*68 + ng*4 + 0] = a01;
        gsh[(gg*2  )*68 + ng*4 + 1] = a10; gsh[(gg*2+1)*68 + ng*4 + 1] = a11;
        gsh[(gg*2  )*68 + ng*4 + 2] = a20; gsh[(gg*2+1)*68 + ng*4 + 2] = a21;
        gsh[(gg*2  )*68 + ng*4 + 3] = a30; gsh[(gg*2+1)*68 + ng*4 + 3] = a31;
        __syncthreads();
        {
            float iv = gsh[(ul_c*4+0)*68 + n_c] + xw0[0];
            float fv = gsh[(ul_c*4+1)*68 + n_c] + xw0[1];
            float gv = gsh[(ul_c*4+2)*68 + n_c] + xw0[2];
            float ov = gsh[(ul_c*4+3)*68 + n_c] + xw0[3];
            c0 = fsig(fv)*c0 + fsig(iv)*__tanhf(gv);
            float h0 = fsig(ov)*__tanhf(c0);
            int ul2 = ul_c + 2;
            float iv1 = gsh[(ul2*4+0)*68 + n_c] + xw1[0];
            float fv1 = gsh[(ul2*4+1)*68 + n_c] + xw1[1];
            float gv1 = gsh[(ul2*4+2)*68 + n_c] + xw1[2];
            float ov1 = gsh[(ul2*4+3)*68 + n_c] + xw1[3];
            c1 = fsig(fv1)*c1 + fsig(iv1)*__tanhf(gv1);
            float h1 = fsig(ov1)*__tanhf(c1);
            int wbuf = (((s+1)&1)*2 + dir)*H2*Ln;
            __stcg(&g_hT[wbuf + (u0+ul_c )*Ln + n_c], h0);
            __stcg(&g_hT[wbuf + (u0+ul2  )*Ln + n_c], h1);
            g_hs[((size_t)t*Ln + n_c)*HIDD + dir*H2 + u0 + ul_c] = h0;
            g_hs[((size_t)t*Ln + n_c)*HIDD + dir*H2 + u0 + ul2 ] = h1;
        }
        if (s < Bz-1) {
            __threadfence();
            __syncthreads();
            if (tid == 0) {
                unsigned c = atomicAdd(&g_barr[dir*8 + s], 1u) + 1u;
                if (c < 64u) {
                    volatile unsigned* p = &g_barr[dir*8 + s];
                    while (*p < 64u) { }
                }
            }
            __syncthreads();
        }
    }
}

// Eisner width-step, 16-lane groups (2 spans/warp). NQ = ceil(w/16).
template<int NQ>
__device__ __forceinline__ void eis_step(
    float* __restrict__ Cr, float* __restrict__ Cl,
    float* __restrict__ Ir, float* __restrict__ Il,
    const float* __restrict__ ush, const float* __restrict__ vsh,
    int w, int spans, int grp, int l16)
{
    bool valid = grp < spans;
    int i = valid ? grp : 0, jn = i + w;
    float t_in[NQ], t_cr[NQ], t_cl[NQ];
    float m_in = -INFINITY, m_cr = -INFINITY, m_cl = -INFINITY;
    #pragma unroll
    for (int q = 0; q < NQ; q++) {
        int o = l16 + q*16;
        t_in[q] = -INFINITY; t_cr[q] = -INFINITY; t_cl[q] = -INFINITY;
        if (valid && o < w) {
            int k = i + o;
            t_in[q] = Cr[i*65 + k] + Cl[(k+1)*65 + jn];
            if (o < w - 1) {
                int k2 = k + 1;
                t_cr[q] = Ir[i*65 + k2] + Cr[k2*65 + jn];
                t_cl[q] = Cl[i*65 + k2] + Il[k2*65 + jn];
            }
        }
        m_in = fmaxf(m_in, t_in[q]);
        m_cr = fmaxf(m_cr, t_cr[q]);
        m_cl = fmaxf(m_cl, t_cl[q]);
    }
    #pragma unroll
    for (int o = 8; o; o >>= 1) {
        m_in = fmaxf(m_in, __shfl_xor_sync(0xffffffffu, m_in, o));
        m_cr = fmaxf(m_cr, __shfl_xor_sync(0xffffffffu, m_cr, o));
        m_cl = fmaxf(m_cl, __shfl_xor_sync(0xffffffffu, m_cl, o));
    }
    float ms_in = fmaxf(m_in, -1e30f);
    float ms_cr = fmaxf(m_cr, -1e30f);
    float ms_cl = fmaxf(m_cl, -1e30f);
    float s_in = 0.f, s_cr = 0.f, s_cl = 0.f;
    #pragma unroll
    for (int q = 0; q < NQ; q++) {
        s_in += __expf(t_in[q] - ms_in);
        s_cr += __expf(t_cr[q] - ms_cr);
        s_cl += __expf(t_cl[q] - ms_cl);
    }
    #pragma unroll
    for (int o = 8; o; o >>= 1) {
        s_in += __shfl_xor_sync(0xffffffffu, s_in, o);
        s_cr += __shfl_xor_sync(0xffffffffu, s_cr, o);
        s_cl += __shfl_xor_sync(0xffffffffu, s_cl, o);
    }
    if (valid && l16 == 0) {
        float inc = ms_in + __logf(s_in);
        float irv = inc + ush[i]  + vsh[jn];
        float ilv = inc + ush[jn] + vsh[i];
        Ir[i*65 + jn] = irv;
        Il[i*65 + jn] = ilv;
        float lcr = ms_cr + __logf(s_cr);
        float M = fmaxf(lcr, irv);
        Cr[i*65 + jn] = M + __logf(__expf(lcr - M) + __expf(irv - M));
        float lcl = ms_cl + __logf(s_cl);
        float Ml = fmaxf(lcl, ilv);
        Cl[i*65 + jn] = Ml + __logf(__expf(lcl - Ml) + __expf(ilv - Ml));
    }
}

// Eisner width-step, 8-lane groups (4 spans/warp). NQ = ceil(w/8), w <= 32.
template<int NQ>
__device__ __forceinline__ void eis_step8(
    float* __restrict__ Cr, float* __restrict__ Cl,
    float* __restrict__ Ir, float* __restrict__ Il,
    const float* __restrict__ ush, const float* __restrict__ vsh,
    int w, int spans, int grp, int l8)
{
    bool valid = grp < spans;
    int i = valid ? grp : 0, jn = i + w;
    float t_in[NQ], t_cr[NQ], t_cl[NQ];
    float m_in = -INFINITY, m_cr = -INFINITY, m_cl = -INFINITY;
    #pragma unroll
    for (int q = 0; q < NQ; q++) {
        int o = l8 + q*8;
        t_in[q] = -INFINITY; t_cr[q] = -INFINITY; t_cl[q] = -INFINITY;
        if (valid && o < w) {
            int k = i + o;
            t_in[q] = Cr[i*65 + k] + Cl[(k+1)*65 + jn];
            if (o < w - 1) {
                int k2 = k + 1;
                t_cr[q] = Ir[i*65 + k2] + Cr[k2*65 + jn];
                t_cl[q] = Cl[i*65 + k2] + Il[k2*65 + jn];
            }
        }
        m_in = fmaxf(m_in, t_in[q]);
        m_cr = fmaxf(m_cr, t_cr[q]);
        m_cl = fmaxf(m_cl, t_cl[q]);
    }
    #pragma unroll
    for (int o = 4; o; o >>= 1) {
        m_in = fmaxf(m_in, __shfl_xor_sync(0xffffffffu, m_in, o));
        m_cr = fmaxf(m_cr, __shfl_xor_sync(0xffffffffu, m_cr, o));
        m_cl = fmaxf(m_cl, __shfl_xor_sync(0xffffffffu, m_cl, o));
    }
    float ms_in = fmaxf(m_in, -1e30f);
    float ms_cr = fmaxf(m_cr, -1e30f);
    float ms_cl = fmaxf(m_cl, -1e30f);
    float s_in = 0.f, s_cr = 0.f, s_cl = 0.f;
    #pragma unroll
    for (int q = 0; q < NQ; q++) {
        s_in += __expf(t_in[q] - ms_in);
        s_cr += __expf(t_cr[q] - ms_cr);
        s_cl += __expf(t_cl[q] - ms_cl);
    }
    #pragma unroll
    for (int o = 4; o; o >>= 1) {
        s_in += __shfl_xor_sync(0xffffffffu, s_in, o);
        s_cr += __shfl_xor_sync(0xffffffffu, s_cr, o);
        s_cl += __shfl_xor_sync(0xffffffffu, s_cl, o);
    }
    if (valid && l8 == 0) {
        float inc = ms_in + __logf(s_in);
        float irv = inc + ush[i]  + vsh[jn];
        float ilv = inc + ush[jn] + vsh[i];
        Ir[i*65 + jn] = irv;
        Il[i*65 + jn] = ilv;
        float lcr = ms_cr + __logf(s_cr);
        float M = fmaxf(lcr, irv);
        Cr[i*65 + jn] = M + __logf(__expf(lcr - M) + __expf(irv - M));
        float lcl = ms_cl + __logf(s_cl);
        float Ml = fmaxf(lcl, ilv);
        Cl[i*65 + jn] = Ml + __logf(__expf(lcl - Ml) + __expf(ilv - Ml));
    }
}

// K3 (tail): blocks 0..7 eisner(+final in blk0); 8..39 scores; 40..55 p12;
// 56..119 uv. Spin deps: uv->eisner (g_barrU), p12->scores (g_barrP).
// Eisner: 8-lane groups for w<=32 (NQ 1..4), 16-lane for w>32; active warps
// <=16 always -> bar.sync 1,512 throughout; w>=49 only 8 warps -> bar.sync 2,256.
__global__ void __launch_bounds__(1024, 1)
k_tail(const float* __restrict__ bs, const int* __restrict__ heads,
       const float* __restrict__ prior, const float* __restrict__ Ws,
       const float* __restrict__ W1, const float* __restrict__ b1,
       const float* __restrict__ W2, const float* __restrict__ b2,
       float* __restrict__ out) {
    extern __shared__ float smf[];
    int tid = threadIdx.x;
    int bid = blockIdx.x;
    if (bid < 8) {
        // ---- Eisner ----
        float* Cr = smf;         float* Cl = smf + 4160;
        float* Ir = smf + 8320;  float* Il = smf + 12480;
        __shared__ float ush[64], vsh[64];
        int b = bid;
        for (int idx = tid; idx < 4160; idx += 1024) {
            int i = idx / 65, jj = idx % 65;
            float dv = (jj < 64 && i == jj) ? 0.0f : NEGV;
            Cr[idx] = dv; Cl[idx] = dv; Ir[idx] = NEGV; Il[idx] = NEGV;
        }
        if (tid == 0) {
            volatile unsigned* p = &g_barrU;
            while (*p < 64u) { }
        }
        __syncthreads();
        if (tid < 64) {
            ush[tid] = __ldcg(&g_u[b*Ln + tid]) + bs[0];
            vsh[tid] = __ldcg(&g_v[b*Ln + tid]);
        }
        __syncthreads();
        int grp8 = tid >> 3, l8 = tid & 7;
        int grp16 = tid >> 4, l16 = tid & 15;
        int wrp = tid >> 5;
        if (wrp < 16) {
            // w 1..32: 8-lane groups, warps 0..15 (active = ceil(spans/4) <= 16)
            for (int w = 1; w <= 8; w++) {
                int spans = Ln - w;
                if (wrp*4 < spans)
                    eis_step8<1>(Cr, Cl, Ir, Il, ush, vsh, w, spans, grp8, l8);
                asm volatile("bar.sync 1, 512;" ::: "memory");
            }
            for (int w = 9; w <= 16; w++) {
                int spans = Ln - w;
                if (wrp*4 < spans)
                    eis_step8<2>(Cr, Cl, Ir, Il, ush, vsh, w, spans, grp8, l8);
                asm volatile("bar.sync 1, 512;" ::: "memory");
            }
            for (int w = 17; w <= 24; w++) {
                int spans = Ln - w;
                if (wrp*4 < spans)
                    eis_step8<3>(Cr, Cl, Ir, Il, ush, vsh, w, spans, grp8, l8);
                asm volatile("bar.sync 1, 512;" ::: "memory");
            }
            for (int w = 25; w <= 32; w++) {
                int spans = Ln - w;
                if (wrp*4 < spans)
                    eis_step8<4>(Cr, Cl, Ir, Il, ush, vsh, w, spans, grp8, l8);
                asm volatile("bar.sync 1, 512;" ::: "memory");
            }
            // w 33..48: 16-lane groups (spans <= 31, active = ceil(spans/2) <= 16)
            for (int w = 33; w <= 48; w++) {
                int spans = Ln - w;
                if (wrp*2 < spans)
                    eis_step<3>(Cr, Cl, Ir, Il, ush, vsh, w, spans, grp16, l16);
                asm volatile("bar.sync 1, 512;" ::: "memory");
            }
            // w 49..63: spans <= 15, active warps <= 8
            if (wrp < 8) {
                for (int w = 49; w <= 63; w++) {
                    int spans = Ln - w;
                    if (wrp*2 < spans)
                        eis_step<4>(Cr, Cl, Ir, Il, ush, vsh, w, spans, grp16, l16);
                    asm volatile("bar.sync 2, 256;" ::: "memory");
                }
            }
        }
        __syncthreads();   // all 32 warps rejoin
        if (tid == 0) g_logZ[b] = Cr[Ln - 1];
        __threadfence();
        __syncthreads();
        if (bid == 0) {
            if (tid == 0) {
                unsigned c = atomicAdd(&g_barr3, 1u) + 1u;
                if (c < 40u) {
                    volatile unsigned* p = &g_barr3;
                    while (*p < 40u) { }
                }
            }
            __syncthreads();
            if (tid < 256) {
                int warp = tid >> 5, lane = tid & 31;
                __shared__ float sb[8];
                int b2 = warp;
                float bsv = bs[0];
                int m1 = lane + 1, m2 = lane + 33;
                float v1, v2;
                {
                    int hd = heads[b2*Ln + m1];
                    v1 = __ldcg(&g_u[b2*Ln + hd]) + __ldcg(&g_v[b2*Ln + m1]) + bsv
                       + __ldcg(&g_s[((size_t)b2*Ln + hd)*Ln + m1])
                       - __ldcg(&g_rowlse[b2*Ln + hd])
                       + prior[((size_t)b2*Ln + hd)*Ln + m1] * (1.0f/64.0f);
                }
                if (m2 < Ln) {
                    int hd = heads[b2*Ln + m2];
                    v2 = __ldcg(&g_u[b2*Ln + hd]) + __ldcg(&g_v[b2*Ln + m2]) + bsv
                       + __ldcg(&g_s[((size_t)b2*Ln + hd)*Ln + m2])
                       - __ldcg(&g_rowlse[b2*Ln + hd])
                       + prior[((size_t)b2*Ln + hd)*Ln + m2] * (1.0f/64.0f);
                } else v2 = -INFINITY;
                float mx = fmaxf(v1, v2);
                #pragma unroll
                for (int o = 16; o; o >>= 1) mx = fmaxf(mx, __shfl_xor_sync(0xffffffffu, mx, o));
                float sum = __expf(v1 - mx) + __expf(v2 - mx);
                #pragma unroll
                for (int o = 16; o; o >>= 1) sum += __shfl_xor_sync(0xffffffffu, sum, o);
                if (lane == 0) sb[b2] = (mx + __logf(sum)) - __ldcg(&g_logZ[b2]);
                __syncthreads();
                if (tid == 0) {
                    float t = 0.f;
                    for (int q = 0; q < 8; q++) t += sb[q];
                    out[0] = -t * (1.0f/8.0f);
                    for (int q = 0; q < 16; q++) g_barr[q] = 0u;
                    g_barr2 = 0u; g_barr3 = 0u; g_barrU = 0u; g_barrP = 0u;
                }
            }
        } else {
            if (tid == 0) atomicAdd(&g_barr3, 1u);
        }
        return;
    }
    if (bid < 40) {
        // ---- scores (waits for p12) ----
        int sb2 = bid - 8;
        int b = sb2 >> 2, i0 = (sb2 & 3) * 16;
        float* p1sh = smf;              // 16 x 132
        float* p2sh = smf + 16*132;     // 64 x 132
        __shared__ float mm[32], ss[32];
        if (tid == 0) {
            volatile unsigned* p = &g_barrP;
            while (*p < 16u) { }
        }
        __syncthreads();
        if (tid < 512) {
            int rr = tid >> 5, e4 = tid & 31;
            *(float4*)&p1sh[rr*132 + e4*4] =
                __ldcg((const float4*)&g_p1[(b*Ln + i0 + rr)*RECD + e4*4]);
        }
        #pragma unroll
        for (int q = 0; q < 2; q++) {
            int li = tid + q*1024;
            int rr = li >> 5, e4 = li & 31;
            *(float4*)&p2sh[rr*132 + e4*4] =
                __ldcg((const float4*)&g_p2[(b*Ln + rr)*RECD + e4*4]);
        }
        __syncthreads();
        int i_l = tid >> 6, j = tid & 63;
        float dot = 0.f;
        #pragma unroll 8
        for (int e4 = 0; e4 < 32; e4++) {
            float4 a = *(const float4*)&p1sh[i_l*132 + e4*4];
            float4 bv = *(const float4*)&p2sh[j*132 + e4*4];
            dot += a.x*bv.x + a.y*bv.y + a.z*bv.z + a.w*bv.w;
        }
        int i = i0 + i_l;
        g_s[((size_t)b*Ln + i)*Ln + j] = dot;
        float m = dot;
        #pragma unroll
        for (int o = 16; o; o >>= 1) m = fmaxf(m, __shfl_xor_sync(0xffffffffu, m, o));
        float sum = __expf(dot - m);
        #pragma unroll
        for (int o = 16; o; o >>= 1) sum += __shfl_xor_sync(0xffffffffu, sum, o);
        int warp = tid >> 5, lane = tid & 31;
        if (lane == 0) { mm[warp] = m; ss[warp] = sum; }
        __syncthreads();
        if (tid < 16) {
            float m0 = mm[tid*2], m1 = mm[tid*2+1];
            float M = fmaxf(m0, m1);
            float S = ss[tid*2]*__expf(m0 - M) + ss[tid*2+1]*__expf(m1 - M);
            g_rowlse[b*Ln + i0 + tid] = M + __logf(S);
        }
        __threadfence();
        __syncthreads();
        if (tid == 0) atomicAdd(&g_barr3, 1u);
        return;
    }
    if (bid < 56) {
        // ---- p12 GEMM: 16 blocks, 4 col-subtiles sharing one h row-tile ----
        int pbi = bid - 40;             // 0..15
        int br = pbi >> 1, cq = pbi & 1;
        int st = tid >> 8;              // subtile 0..3
        int stid = tid & 255;
        int bc = cq*4 + st;
        const float* W    = (bc < 4) ? W1 : W2;
        const float* bias = (bc < 4) ? b1 : b2;
        float* dst        = (bc < 4) ? g_p1 : g_p2;
        int c0 = (bc & 3) * 32;
        int r0 = br * 64;
        float* hsh = smf;                         // 64k x 64row pitch 68
        float* wsh = smf + 4352 + st*2176;        // 32c x 64k pitch 68
        int tr = stid >> 4, tc = stid & 15;
        float a0[2] = {}, a1[2] = {}, a2[2] = {}, a3[2] = {};
        int srow = tid & 63, skq = tid >> 6;      // 0..15
        int swc = stid >> 3, swk8 = (stid & 7) * 8;
        for (int k0 = 0; k0 < HIDD; k0 += 64) {
            float4 v = *(const float4*)&g_hs[(size_t)(r0+srow)*HIDD + k0 + skq*4];
            int kb = skq*4;
            hsh[(kb+0)*68+srow]=v.x; hsh[(kb+1)*68+srow]=v.y;
            hsh[(kb+2)*68+srow]=v.z; hsh[(kb+3)*68+srow]=v.w;
            *(float4*)&wsh[swc*68 + swk8] =
                *(const float4*)&W[(size_t)(c0 + swc)*HIDD + k0 + swk8];
            *(float4*)&wsh[swc*68 + swk8 + 4] =
                *(const float4*)&W[(size_t)(c0 + swc)*HIDD + k0 + swk8 + 4];
            __syncthreads();
            #pragma unroll 8
            for (int k = 0; k < 64; k += 4) {
                float4 w0 = *(const float4*)&wsh[(tc*2  )*68 + k];
                float4 w1 = *(const float4*)&wsh[(tc*2+1)*68 + k];
                float4 h0 = *(const float4*)&hsh[(k+0)*68 + tr*4];
                float4 h1 = *(const float4*)&hsh[(k+1)*68 + tr*4];
                float4 h2 = *(const float4*)&hsh[(k+2)*68 + tr*4];
                float4 h3 = *(const float4*)&hsh[(k+3)*68 + tr*4];
                a0[0] += h0.x*w0.x + h1.x*w0.y + h2.x*w0.z + h3.x*w0.w;
                a1[0] += h0.y*w0.x + h1.y*w0.y + h2.y*w0.z + h3.y*w0.w;
                a2[0] += h0.z*w0.x + h1.z*w0.y + h2.z*w0.z + h3.z*w0.w;
                a3[0] += h0.w*w0.x + h1.w*w0.y + h2.w*w0.z + h3.w*w0.w;
                a0[1] += h0.x*w1.x + h1.x*w1.y + h2.x*w1.z + h3.x*w1.w;
                a1[1] += h0.y*w1.x + h1.y*w1.y + h2.y*w1.z + h3.y*w1.w;
                a2[1] += h0.z*w1.x + h1.z*w1.y + h2.z*w1.z + h3.z*w1.w;
                a3[1] += h0.w*w1.x + h1.w*w1.y + h2.w*w1.z + h3.w*w1.w;
            }
            __syncthreads();
        }
        int cc = c0 + tc*2;
        float2 bv = { bias[cc], bias[cc+1] };
        *(float2*)&dst[(r0 + tr*4 + 0)*RECD + cc] = make_float2(a0[0]+bv.x, a0[1]+bv.y);
        *(float2*)&dst[(r0 + tr*4 + 1)*RECD + cc] = make_float2(a1[0]+bv.x, a1[1]+bv.y);
        *(float2*)&dst[(r0 + tr*4 + 2)*RECD + cc] = make_float2(a2[0]+bv.x, a2[1]+bv.y);
        *(float2*)&dst[(r0 + tr*4 + 3)*RECD + cc] = make_float2(a3[0]+bv.x, a3[1]+bv.y);
        __threadfence();
        __syncthreads();
        if (tid == 0) atomicAdd(&g_barrP, 1u);
        return;
    }
    // ---- uv: 64 blocks x 8 rows ----
    {
        __shared__ float pu[32], pv[32];
        int row = (bid - 56)*8 + (tid >> 7);
        int t128 = tid & 127;
        int l = row & 63;
        const float4* hc = (const float4*)&g_hs[(size_t)row*HIDD];
        const float4* W4 = (const float4*)Ws;
        float4 h0 = hc[t128];
        float4 wu0 = W4[t128], wv0 = W4[384 + t128];
        float au = h0.x*wu0.x + h0.y*wu0.y + h0.z*wu0.z + h0.w*wu0.w;
        float av = h0.x*wv0.x + h0.y*wv0.y + h0.z*wv0.z + h0.w*wv0.w;
        if (l > 0) {
            float4 hb = hc[t128 - 128];
            float4 wu = W4[128 + t128], wv = W4[512 + t128];
            au += hb.x*wu.x + hb.y*wu.y + hb.z*wu.z + hb.w*wu.w;
            av += hb.x*wv.x + hb.y*wv.y + hb.z*wv.z + hb.w*wv.w;
        }
        if (l < 63) {
            float4 hn = hc[t128 + 128];
            float4 wu = W4[256 + t128], wv = W4[640 + t128];
            au += hn.x*wu.x + hn.y*wu.y + hn.z*wu.z + hn.w*wu.w;
            av += hn.x*wv.x + hn.y*wv.y + hn.z*wv.z + hn.w*wv.w;
        }
        #pragma unroll
        for (int o = 16; o; o >>= 1) {
            au += __shfl_xor_sync(0xffffffffu, au, o);
            av += __shfl_xor_sync(0xffffffffu, av, o);
        }
        int warp = tid >> 5, lane = tid & 31;
        if (lane == 0) { pu[warp] = au; pv[warp] = av; }
        __syncthreads();
        if (t128 == 0) {
            int wb = (tid >> 7)*4;
            g_u[row] = pu[wb]+pu[wb+1]+pu[wb+2]+pu[wb+3];
            g_v[row] = pv[wb]+pv[wb+1]+pv[wb+2]+pv[wb+3];
        }
        __threadfence();
        __syncthreads();
        if (tid == 0) atomicAdd(&g_barrU, 1u);
    }
}

extern "C" void kernel_launch(void* const* d_in, const int* in_sizes, int n_in,
                              void* d_out, int out_size) {
    const int*   sents = (const int*)  d_in[0];
    const float* mask  = (const float*)d_in[1];
    const float* prior = (const float*)d_in[2];
    const int*   heads = (const int*)  d_in[3];
    const float* emb   = (const float*)d_in[4];
    const float* Wih_f = (const float*)d_in[5];
    const float* Whh_f = (const float*)d_in[6];
    const float* bih_f = (const float*)d_in[7];
    const float* bhh_f = (const float*)d_in[8];
    const float* Wih_b = (const float*)d_in[9];
    const float* Whh_b = (const float*)d_in[10];
    const float* bih_b = (const float*)d_in[11];
    const float* bhh_b = (const float*)d_in[12];
    const float* W1    = (const float*)d_in[13];
    const float* b1    = (const float*)d_in[14];
    const float* W2    = (const float*)d_in[15];
    const float* b2    = (const float*)d_in[16];
    const float* Ws    = (const float*)d_in[17];
    const float* bsv   = (const float*)d_in[18];
    float* out = (float*)d_out;
    (void)in_sizes; (void)n_in; (void)out_size;

    cudaFuncSetAttribute(k_lstm_all, cudaFuncAttributeMaxDynamicSharedMemorySize, 22656*4);
    cudaFuncSetAttribute(k_tail,     cudaFuncAttributeMaxDynamicSharedMemorySize, 16640*4);

    dim3 g1(8, 16, 2);
    k_emb_xw<<<g1, 256>>>(sents, mask, emb, Wih_f, bih_f, bhh_f, Wih_b, bih_b, bhh_b);
    k_lstm_all<<<128, 128, 22656*4>>>(Whh_f, Whh_b);
    k_tail<<<120, 1024, 16640*4>>>(bsv, heads, prior, Ws, W1, b1, W2, b2, out);
}